// round 1
// baseline (speedup 1.0000x reference)
#include <cuda_runtime.h>

// ---------------- problem constants ----------------
#define NN 100000
#define VV 3
#define EE 500000
#define EPSL 1e-5f

#define BN 64          // nodes per tile
#define BNP 65         // padded pitch for k-major tiles
#define NT 256         // threads per block
#define NTILES ((NN + BN - 1) / BN)

// ---------------- scratch (device globals; no allocation) ----------------
__device__ float g_pre[(size_t)VV * NN * 128];        // segment-summed weighted features
__device__ float g_wsum[VV * NN];                     // segment-summed edge weights
__device__ float g_selfout[(size_t)NN * 128];
__device__ float g_transformed[(size_t)NN * 128];
__device__ float g_nodeatt[NN];
__device__ float g_viewout[(size_t)VV * NN * 128];
__device__ float g_vscore[VV * NN];

// ---------------- zero scratch ----------------
__global__ void k_zero() {
    size_t tid = (size_t)blockIdx.x * blockDim.x + threadIdx.x;
    size_t stride = (size_t)gridDim.x * blockDim.x;
    size_t total4 = ((size_t)VV * NN * 128) / 4;
    float4 z = make_float4(0.f, 0.f, 0.f, 0.f);
    for (size_t i = tid; i < total4; i += stride)
        reinterpret_cast<float4*>(g_pre)[i] = z;
    for (size_t i = tid; i < (size_t)VV * NN; i += stride)
        g_wsum[i] = 0.f;
}

// ---------------- edge scatter: pre[v,dst] += w * features[src]; wsum += w ----------------
// one warp per edge, vector reductions (16B red ops)
__global__ void __launch_bounds__(NT) k_edge(const int* __restrict__ src,
                                             const int* __restrict__ dst,
                                             const float* __restrict__ w,
                                             const float* __restrict__ feats) {
    int gw = (int)(((size_t)blockIdx.x * NT + threadIdx.x) >> 5);
    if (gw >= VV * EE) return;
    int l = threadIdx.x & 31;
    int v = gw / EE;
    int s = src[gw];
    int d = dst[gw];
    float we = w[gw];
    float4 x = reinterpret_cast<const float4*>(feats + (size_t)s * 128)[l];
    float* p = g_pre + ((size_t)v * NN + d) * 128 + l * 4;
    asm volatile("red.global.add.v4.f32 [%0], {%1,%2,%3,%4};" ::
                 "l"(p), "f"(we * x.x), "f"(we * x.y), "f"(we * x.z), "f"(we * x.w)
                 : "memory");
    if (l == 0) atomicAdd(&g_wsum[v * NN + d], we);
}

// ---------------- shared helpers ----------------
// load 64-node tile of a [*,128] row-major matrix into k-major shared tile Fs[k][n], pitch BNP
__device__ __forceinline__ void load_tileT(const float* __restrict__ g, int nb, float* __restrict__ Fs) {
    int t = threadIdx.x, w = t >> 5, l = t & 31;
#pragma unroll
    for (int r = 0; r < 8; ++r) {
        int grp = r * 8 + w;                 // 0..63
        int i = (grp & 15) * 4 + (l >> 3);   // node 0..63
        int kq = (grp >> 4) * 8 + (l & 7);   // float4 index 0..31
        int n = nb + i;
        float4 v = make_float4(0.f, 0.f, 0.f, 0.f);
        if (n < NN) v = reinterpret_cast<const float4*>(g + (size_t)n * 128)[kq];
        int k = kq * 4;
        Fs[(k + 0) * BNP + i] = v.x;
        Fs[(k + 1) * BNP + i] = v.y;
        Fs[(k + 2) * BNP + i] = v.z;
        Fs[(k + 3) * BNP + i] = v.w;
    }
}

__device__ __forceinline__ void load_w(const float* __restrict__ g, float* __restrict__ Ws, int n4) {
    for (int idx = threadIdx.x; idx < n4; idx += NT)
        reinterpret_cast<float4*>(Ws)[idx] = reinterpret_cast<const float4*>(g)[idx];
}

// register-blocked matmul: acc[4][TN] += Fs[:, ng*4..+3]^T @ Ws[:, cg*TN..]
template <int KDIM, int OC, int TN>
__device__ __forceinline__ void mm_tile(const float* __restrict__ Fs, const float* __restrict__ Ws,
                                        float acc[4][TN], int ng, int cg) {
    const int n0 = ng * 4;
#pragma unroll 8
    for (int k = 0; k < KDIM; ++k) {
        float a0 = Fs[k * BNP + n0 + 0];
        float a1 = Fs[k * BNP + n0 + 1];
        float a2 = Fs[k * BNP + n0 + 2];
        float a3 = Fs[k * BNP + n0 + 3];
        const float4* bp = reinterpret_cast<const float4*>(Ws + k * OC + cg * TN);
        float4 b0 = bp[0];
        if (TN == 8) {
            float4 b1 = bp[1];
            float bv[8] = {b0.x, b0.y, b0.z, b0.w, b1.x, b1.y, b1.z, b1.w};
#pragma unroll
            for (int j = 0; j < 8; ++j) {
                acc[0][j] = fmaf(a0, bv[j], acc[0][j]);
                acc[1][j] = fmaf(a1, bv[j], acc[1][j]);
                acc[2][j] = fmaf(a2, bv[j], acc[2][j]);
                acc[3][j] = fmaf(a3, bv[j], acc[3][j]);
            }
        } else {
            float bv[4] = {b0.x, b0.y, b0.z, b0.w};
#pragma unroll
            for (int j = 0; j < 4; ++j) {
                acc[0][j] = fmaf(a0, bv[j], acc[0][j]);
                acc[1][j] = fmaf(a1, bv[j], acc[1][j]);
                acc[2][j] = fmaf(a2, bv[j], acc[2][j]);
                acc[3][j] = fmaf(a3, bv[j], acc[3][j]);
            }
        }
    }
}

// ---------------- feature-side kernel ----------------
// computes: class_probs -> out_cp, node_att -> g_nodeatt,
//           self_out -> g_selfout, transformed -> g_transformed
__global__ void __launch_bounds__(NT, 2) k_feat(
    const float* __restrict__ feats,
    const float* __restrict__ clsW, const float* __restrict__ clsb,
    const float* __restrict__ attW1, const float* __restrict__ attb1,
    const float* __restrict__ attW2, const float* __restrict__ attb2,
    const float* __restrict__ attbias,
    const float* __restrict__ selfW, const float* __restrict__ selfb,
    const float* __restrict__ featW, const float* __restrict__ featb,
    float* __restrict__ out_cp) {
    extern __shared__ float sm[];
    float* Fs = sm;                  // 128*BNP
    float* Wbuf = Fs + 128 * BNP;    // 16384
    float* clsWs = Wbuf + 16384;     // 256
    float* red = clsWs + 256;        // 16*64
    float* scoreS = red + 1024;      // 128

    int nb = blockIdx.x * BN;
    int ng = threadIdx.x >> 4, cg = threadIdx.x & 15;

    load_tileT(feats, nb, Fs);
    load_w(selfW, Wbuf, 4096);
    load_w(clsW, clsWs, 64);
    __syncthreads();

    float acc[4][8];

    // ---- self_out = f @ selfW + selfb ----
#pragma unroll
    for (int i = 0; i < 4; ++i)
#pragma unroll
        for (int j = 0; j < 8; ++j) acc[i][j] = 0.f;
    mm_tile<128, 128, 8>(Fs, Wbuf, acc, ng, cg);
    {
        float4 sb0 = __ldg(reinterpret_cast<const float4*>(selfb + cg * 8));
        float4 sb1 = __ldg(reinterpret_cast<const float4*>(selfb + cg * 8) + 1);
#pragma unroll
        for (int i = 0; i < 4; ++i) {
            int n = nb + ng * 4 + i;
            if (n < NN) {
                float4 o0 = make_float4(acc[i][0] + sb0.x, acc[i][1] + sb0.y, acc[i][2] + sb0.z, acc[i][3] + sb0.w);
                float4 o1 = make_float4(acc[i][4] + sb1.x, acc[i][5] + sb1.y, acc[i][6] + sb1.z, acc[i][7] + sb1.w);
                float4* o = reinterpret_cast<float4*>(g_selfout + (size_t)n * 128 + cg * 8);
                o[0] = o0; o[1] = o1;
            }
        }
    }
    __syncthreads();
    load_w(featW, Wbuf, 4096);
    __syncthreads();

    // ---- transformed = f @ featW + featb ----
#pragma unroll
    for (int i = 0; i < 4; ++i)
#pragma unroll
        for (int j = 0; j < 8; ++j) acc[i][j] = 0.f;
    mm_tile<128, 128, 8>(Fs, Wbuf, acc, ng, cg);
    {
        float4 fb0 = __ldg(reinterpret_cast<const float4*>(featb + cg * 8));
        float4 fb1 = __ldg(reinterpret_cast<const float4*>(featb + cg * 8) + 1);
#pragma unroll
        for (int i = 0; i < 4; ++i) {
            int n = nb + ng * 4 + i;
            if (n < NN) {
                float4 o0 = make_float4(acc[i][0] + fb0.x, acc[i][1] + fb0.y, acc[i][2] + fb0.z, acc[i][3] + fb0.w);
                float4 o1 = make_float4(acc[i][4] + fb1.x, acc[i][5] + fb1.y, acc[i][6] + fb1.z, acc[i][7] + fb1.w);
                float4* o = reinterpret_cast<float4*>(g_transformed + (size_t)n * 128 + cg * 8);
                o[0] = o0; o[1] = o1;
            }
        }
    }
    __syncthreads();
    // ---- attW1 rearranged: Wbuf[d][c*64+h] = attW1[c][d][h] ----
    for (int idx = threadIdx.x; idx < 2 * 128 * 16; idx += NT) {
        int h4 = idx & 15;
        int d = (idx >> 4) & 127;
        int c = idx >> 11;
        reinterpret_cast<float4*>(Wbuf + d * 128 + c * 64)[h4] =
            __ldg(reinterpret_cast<const float4*>(attW1) + idx);
    }
    __syncthreads();

    // ---- h = relu(f @ attW1 + attb1); partial score dot with attW2 ----
#pragma unroll
    for (int i = 0; i < 4; ++i)
#pragma unroll
        for (int j = 0; j < 8; ++j) acc[i][j] = 0.f;
    mm_tile<128, 128, 8>(Fs, Wbuf, acc, ng, cg);
#pragma unroll
    for (int i = 0; i < 4; ++i) {
        float p = 0.f;
#pragma unroll
        for (int j = 0; j < 8; ++j) {
            int c = cg * 8 + j;   // c = cl*64 + h, attb1/attW2 are flat [C*H]
            float hv = fmaxf(acc[i][j] + __ldg(attb1 + c), 0.f);
            p = fmaf(hv, __ldg(attW2 + c), p);
        }
        red[cg * 64 + ng * 4 + i] = p;
    }
    __syncthreads();
    if (threadIdx.x < 128) {
        int nl = threadIdx.x & 63, cl = threadIdx.x >> 6;
        float s = 0.f;
#pragma unroll
        for (int q = 0; q < 8; ++q) s += red[(cl * 8 + q) * 64 + nl];
        s += __ldg(attb2 + cl);
        scoreS[cl * 64 + nl] = 1.f / (1.f + expf(-s));
    }
    __syncthreads();
    if (threadIdx.x < 64) {
        int nl = threadIdx.x, n = nb + nl;
        if (n < NN) {
            float l0 = __ldg(clsb), l1 = __ldg(clsb + 1);
            for (int k = 0; k < 128; ++k) {
                float f = Fs[k * BNP + nl];
                l0 = fmaf(f, clsWs[k * 2], l0);
                l1 = fmaf(f, clsWs[k * 2 + 1], l1);
            }
            float m = fmaxf(l0, l1);
            float e0 = expf(l0 - m), e1 = expf(l1 - m);
            float inv = 1.f / (e0 + e1);
            float cp0 = e0 * inv, cp1 = e1 * inv;
            out_cp[(size_t)n * 2] = cp0;
            out_cp[(size_t)n * 2 + 1] = cp1;
            g_nodeatt[n] = scoreS[nl] * cp0 + scoreS[64 + nl] * cp1 + __ldg(attbias);
        }
    }
}

// ---------------- per-view kernel ----------------
// agg = pre@relW + wsum*relb ; gate = sigmoid(agg@gateW + gateb) ; view_out = gate*agg
// vscore = relu((view_out*view_pref)@vattW1 + vattb1) . vattW2 + vattb2
__global__ void __launch_bounds__(NT, 2) k_view(
    const float* __restrict__ relW, const float* __restrict__ relb,
    const float* __restrict__ gateW, const float* __restrict__ gateb,
    const float* __restrict__ view_pref,
    const float* __restrict__ vattW1, const float* __restrict__ vattb1,
    const float* __restrict__ vattW2, const float* __restrict__ vattb2) {
    extern __shared__ float sm[];
    float* buf = sm;                 // 128*BNP  (Ps -> As -> VOs)
    float* Wbuf = buf + 128 * BNP;   // 16384
    float* wsumS = Wbuf + 16384;     // 64
    float* red = wsumS + 64;         // 1024

    int v = blockIdx.y;
    int nb = blockIdx.x * BN;
    int ng = threadIdx.x >> 4, cg = threadIdx.x & 15;

    load_tileT(g_pre + (size_t)v * NN * 128, nb, buf);
    load_w(relW + (size_t)v * 16384, Wbuf, 4096);
    if (threadIdx.x < 64) {
        int n = nb + threadIdx.x;
        wsumS[threadIdx.x] = (n < NN) ? g_wsum[v * NN + n] : 0.f;
    }
    __syncthreads();

    // ---- agg ----
    float acc[4][8];
#pragma unroll
    for (int i = 0; i < 4; ++i)
#pragma unroll
        for (int j = 0; j < 8; ++j) acc[i][j] = 0.f;
    mm_tile<128, 128, 8>(buf, Wbuf, acc, ng, cg);
    {
        float4 rb0 = __ldg(reinterpret_cast<const float4*>(relb + v * 128 + cg * 8));
        float4 rb1 = __ldg(reinterpret_cast<const float4*>(relb + v * 128 + cg * 8) + 1);
        float rb[8] = {rb0.x, rb0.y, rb0.z, rb0.w, rb1.x, rb1.y, rb1.z, rb1.w};
#pragma unroll
        for (int i = 0; i < 4; ++i) {
            float ws = wsumS[ng * 4 + i];
#pragma unroll
            for (int j = 0; j < 8; ++j) acc[i][j] = fmaf(ws, rb[j], acc[i][j]);
        }
    }
    __syncthreads();   // all threads done reading Ps + relW
    // stash agg tile k-major for the gate matmul
#pragma unroll
    for (int i = 0; i < 4; ++i)
#pragma unroll
        for (int j = 0; j < 8; ++j)
            buf[(cg * 8 + j) * BNP + ng * 4 + i] = acc[i][j];
    load_w(gateW + (size_t)v * 16384, Wbuf, 4096);
    __syncthreads();

    // ---- gate, view_out ----
    float gac[4][8];
#pragma unroll
    for (int i = 0; i < 4; ++i)
#pragma unroll
        for (int j = 0; j < 8; ++j) gac[i][j] = 0.f;
    mm_tile<128, 128, 8>(buf, Wbuf, gac, ng, cg);
    {
        float4 gb0 = __ldg(reinterpret_cast<const float4*>(gateb + v * 128 + cg * 8));
        float4 gb1 = __ldg(reinterpret_cast<const float4*>(gateb + v * 128 + cg * 8) + 1);
        float gb[8] = {gb0.x, gb0.y, gb0.z, gb0.w, gb1.x, gb1.y, gb1.z, gb1.w};
#pragma unroll
        for (int i = 0; i < 4; ++i)
#pragma unroll
            for (int j = 0; j < 8; ++j) {
                float gate = 1.f / (1.f + expf(-(gac[i][j] + gb[j])));
                gac[i][j] = gate * acc[i][j];   // gac now holds view_out
            }
    }
#pragma unroll
    for (int i = 0; i < 4; ++i) {
        int n = nb + ng * 4 + i;
        if (n < NN) {
            float4* o = reinterpret_cast<float4*>(g_viewout + ((size_t)v * NN + n) * 128 + cg * 8);
            o[0] = make_float4(gac[i][0], gac[i][1], gac[i][2], gac[i][3]);
            o[1] = make_float4(gac[i][4], gac[i][5], gac[i][6], gac[i][7]);
        }
    }
    __syncthreads();   // all threads done reading As + gateW
    // stash view_out * view_pref for the view-attention matmul
    {
        float4 vp0 = __ldg(reinterpret_cast<const float4*>(view_pref + v * 128 + cg * 8));
        float4 vp1 = __ldg(reinterpret_cast<const float4*>(view_pref + v * 128 + cg * 8) + 1);
        float vp[8] = {vp0.x, vp0.y, vp0.z, vp0.w, vp1.x, vp1.y, vp1.z, vp1.w};
#pragma unroll
        for (int i = 0; i < 4; ++i)
#pragma unroll
            for (int j = 0; j < 8; ++j)
                buf[(cg * 8 + j) * BNP + ng * 4 + i] = gac[i][j] * vp[j];
    }
    load_w(vattW1, Wbuf, 2048);
    __syncthreads();

    // ---- view-attention score ----
    float vac[4][4];
#pragma unroll
    for (int i = 0; i < 4; ++i)
#pragma unroll
        for (int j = 0; j < 4; ++j) vac[i][j] = 0.f;
    mm_tile<128, 64, 4>(buf, Wbuf, vac, ng, cg);
    {
        float4 vb = __ldg(reinterpret_cast<const float4*>(vattb1 + cg * 4));
        float4 vw = __ldg(reinterpret_cast<const float4*>(vattW2 + cg * 4));
        float vbb[4] = {vb.x, vb.y, vb.z, vb.w};
        float vww[4] = {vw.x, vw.y, vw.z, vw.w};
#pragma unroll
        for (int i = 0; i < 4; ++i) {
            float s = 0.f;
#pragma unroll
            for (int j = 0; j < 4; ++j) {
                float vh = fmaxf(vac[i][j] + vbb[j], 0.f);
                s = fmaf(vh, vww[j], s);
            }
            red[cg * 64 + ng * 4 + i] = s;
        }
    }
    __syncthreads();
    if (threadIdx.x < 64) {
        int nl = threadIdx.x, n = nb + nl;
        if (n < NN) {
            float s = __ldg(vattb2);
#pragma unroll
            for (int q = 0; q < 16; ++q) s += red[q * 64 + nl];
            g_vscore[v * NN + n] = s;
        }
    }
}

// ---------------- fusion + residual + layer norm ----------------
__global__ void __launch_bounds__(NT, 1) k_fuse(
    const float* __restrict__ fusW, const float* __restrict__ fusb,
    const float* __restrict__ ln_g, const float* __restrict__ ln_b,
    float* __restrict__ out) {
    extern __shared__ float sm[];
    float* Zs = sm;                  // 256*BNP
    float* Wf = Zs + 256 * BNP;      // 32768
    float* vwA = Wf + 32768;         // 3*64 (view weight * node_att)
    float* redA = vwA + 192;         // 1024
    float* redB = redA + 1024;       // 1024
    float* muS = redB + 1024;        // 64
    float* rsS = muS + 64;           // 64

    int nb = blockIdx.x * BN;
    int ng = threadIdx.x >> 4, cg = threadIdx.x & 15;

    if (threadIdx.x < 64) {
        int nl = threadIdx.x, n = nb + nl;
        float s0 = 0.f, s1 = 0.f, s2 = 0.f, na = 0.f;
        if (n < NN) {
            s0 = g_vscore[n];
            s1 = g_vscore[NN + n];
            s2 = g_vscore[2 * NN + n];
            na = g_nodeatt[n];
        }
        float m = fmaxf(s0, fmaxf(s1, s2));
        float e0 = expf(s0 - m), e1 = expf(s1 - m), e2 = expf(s2 - m);
        float inv = na / (e0 + e1 + e2);
        vwA[nl] = e0 * inv;
        vwA[64 + nl] = e1 * inv;
        vwA[128 + nl] = e2 * inv;
    }
    load_w(fusW, Wf, 8192);
    __syncthreads();

    // rows 0..127: self_out
    load_tileT(g_selfout, nb, Zs);
    // rows 128..255: weighted = (sum_v vw*view_out) * node_att
    {
        int t = threadIdx.x, w = t >> 5, l = t & 31;
#pragma unroll
        for (int r = 0; r < 8; ++r) {
            int grp = r * 8 + w;
            int i = (grp & 15) * 4 + (l >> 3);
            int kq = (grp >> 4) * 8 + (l & 7);
            int n = nb + i;
            float4 a = make_float4(0.f, 0.f, 0.f, 0.f);
            if (n < NN) {
                float w0 = vwA[i], w1 = vwA[64 + i], w2 = vwA[128 + i];
                float4 x0 = reinterpret_cast<const float4*>(g_viewout + (size_t)n * 128)[kq];
                float4 x1 = reinterpret_cast<const float4*>(g_viewout + ((size_t)NN + n) * 128)[kq];
                float4 x2 = reinterpret_cast<const float4*>(g_viewout + ((size_t)2 * NN + n) * 128)[kq];
                a.x = w0 * x0.x + w1 * x1.x + w2 * x2.x;
                a.y = w0 * x0.y + w1 * x1.y + w2 * x2.y;
                a.z = w0 * x0.z + w1 * x1.z + w2 * x2.z;
                a.w = w0 * x0.w + w1 * x1.w + w2 * x2.w;
            }
            int k = 128 + kq * 4;
            Zs[(k + 0) * BNP + i] = a.x;
            Zs[(k + 1) * BNP + i] = a.y;
            Zs[(k + 2) * BNP + i] = a.z;
            Zs[(k + 3) * BNP + i] = a.w;
        }
    }
    __syncthreads();

    float acc[4][8];
#pragma unroll
    for (int i = 0; i < 4; ++i)
#pragma unroll
        for (int j = 0; j < 8; ++j) acc[i][j] = 0.f;
    mm_tile<256, 128, 8>(Zs, Wf, acc, ng, cg);

    {
        float4 fb0 = __ldg(reinterpret_cast<const float4*>(fusb + cg * 8));
        float4 fb1 = __ldg(reinterpret_cast<const float4*>(fusb + cg * 8) + 1);
        float fb[8] = {fb0.x, fb0.y, fb0.z, fb0.w, fb1.x, fb1.y, fb1.z, fb1.w};
#pragma unroll
        for (int i = 0; i < 4; ++i) {
            int n = nb + ng * 4 + i;
            float tr[8] = {0.f, 0.f, 0.f, 0.f, 0.f, 0.f, 0.f, 0.f};
            if (n < NN) {
                float4 t0 = reinterpret_cast<const float4*>(g_transformed + (size_t)n * 128 + cg * 8)[0];
                float4 t1 = reinterpret_cast<const float4*>(g_transformed + (size_t)n * 128 + cg * 8)[1];
                tr[0] = t0.x; tr[1] = t0.y; tr[2] = t0.z; tr[3] = t0.w;
                tr[4] = t1.x; tr[5] = t1.y; tr[6] = t1.z; tr[7] = t1.w;
            }
            float s = 0.f, s2 = 0.f;
#pragma unroll
            for (int j = 0; j < 8; ++j) {
                float f = fmaxf(acc[i][j] + fb[j], 0.f) + tr[j];
                acc[i][j] = f;
                s += f;
                s2 = fmaf(f, f, s2);
            }
            redA[cg * 64 + ng * 4 + i] = s;
            redB[cg * 64 + ng * 4 + i] = s2;
        }
    }
    __syncthreads();
    if (threadIdx.x < 64) {
        int nl = threadIdx.x;
        float sa = 0.f, sb = 0.f;
#pragma unroll
        for (int q = 0; q < 16; ++q) {
            sa += redA[q * 64 + nl];
            sb += redB[q * 64 + nl];
        }
        float mu = sa * (1.f / 128.f);
        float var = sb * (1.f / 128.f) - mu * mu;
        muS[nl] = mu;
        rsS[nl] = rsqrtf(var + EPSL);
    }
    __syncthreads();
    {
        float4 lg0 = __ldg(reinterpret_cast<const float4*>(ln_g + cg * 8));
        float4 lg1 = __ldg(reinterpret_cast<const float4*>(ln_g + cg * 8) + 1);
        float4 lb0 = __ldg(reinterpret_cast<const float4*>(ln_b + cg * 8));
        float4 lb1 = __ldg(reinterpret_cast<const float4*>(ln_b + cg * 8) + 1);
        float lg[8] = {lg0.x, lg0.y, lg0.z, lg0.w, lg1.x, lg1.y, lg1.z, lg1.w};
        float lb[8] = {lb0.x, lb0.y, lb0.z, lb0.w, lb1.x, lb1.y, lb1.z, lb1.w};
#pragma unroll
        for (int i = 0; i < 4; ++i) {
            int nl = ng * 4 + i;
            int n = nb + nl;
            if (n < NN) {
                float mu = muS[nl], rs = rsS[nl];
                float o[8];
#pragma unroll
                for (int j = 0; j < 8; ++j)
                    o[j] = (acc[i][j] - mu) * rs * lg[j] + lb[j];
                float4* op = reinterpret_cast<float4*>(out + (size_t)n * 128 + cg * 8);
                op[0] = make_float4(o[0], o[1], o[2], o[3]);
                op[1] = make_float4(o[4], o[5], o[6], o[7]);
            }
        }
    }
}

// ---------------- launch ----------------
extern "C" void kernel_launch(void* const* d_in, const int* in_sizes, int n_in,
                              void* d_out, int out_size) {
    const float* feats   = (const float*)d_in[0];
    const int*   esrc    = (const int*)d_in[1];
    const int*   edst    = (const int*)d_in[2];
    const float* ew      = (const float*)d_in[3];
    const float* clsW    = (const float*)d_in[4];
    const float* clsb    = (const float*)d_in[5];
    const float* attW1   = (const float*)d_in[6];
    const float* attb1   = (const float*)d_in[7];
    const float* attW2   = (const float*)d_in[8];
    const float* attb2   = (const float*)d_in[9];
    const float* attbias = (const float*)d_in[10];
    const float* relW    = (const float*)d_in[11];
    const float* relb    = (const float*)d_in[12];
    const float* gateW   = (const float*)d_in[13];
    const float* gateb   = (const float*)d_in[14];
    const float* vpref   = (const float*)d_in[15];
    const float* vattW1  = (const float*)d_in[16];
    const float* vattb1  = (const float*)d_in[17];
    const float* vattW2  = (const float*)d_in[18];
    const float* vattb2  = (const float*)d_in[19];
    const float* selfW   = (const float*)d_in[20];
    const float* selfb   = (const float*)d_in[21];
    const float* featW   = (const float*)d_in[22];
    const float* featb   = (const float*)d_in[23];
    const float* fusW    = (const float*)d_in[24];
    const float* fusb    = (const float*)d_in[25];
    const float* lng     = (const float*)d_in[26];
    const float* lnb     = (const float*)d_in[27];

    float* out = (float*)d_out;
    float* out_cp = out + (size_t)NN * 128;

    const int SMEM_FEAT = (128 * BNP + 16384 + 256 + 1024 + 128) * 4;
    const int SMEM_VIEW = (128 * BNP + 16384 + 64 + 1024) * 4;
    const int SMEM_FUSE = (256 * BNP + 32768 + 192 + 1024 + 1024 + 64 + 64) * 4;

    cudaFuncSetAttribute(k_feat, cudaFuncAttributeMaxDynamicSharedMemorySize, SMEM_FEAT);
    cudaFuncSetAttribute(k_view, cudaFuncAttributeMaxDynamicSharedMemorySize, SMEM_VIEW);
    cudaFuncSetAttribute(k_fuse, cudaFuncAttributeMaxDynamicSharedMemorySize, SMEM_FUSE);

    k_zero<<<2048, NT>>>();

    {
        long long warps = (long long)VV * EE;
        int blocks = (int)((warps * 32 + NT - 1) / NT);
        k_edge<<<blocks, NT>>>(esrc, edst, ew, feats);
    }

    k_feat<<<NTILES, NT, SMEM_FEAT>>>(feats, clsW, clsb, attW1, attb1, attW2, attb2,
                                      attbias, selfW, selfb, featW, featb, out_cp);

    dim3 gv(NTILES, VV);
    k_view<<<gv, NT, SMEM_VIEW>>>(relW, relb, gateW, gateb, vpref,
                                  vattW1, vattb1, vattW2, vattb2);

    k_fuse<<<NTILES, NT, SMEM_FUSE>>>(fusW, fusb, lng, lnb, out);
}

// round 2
// speedup vs baseline: 1.0011x; 1.0011x over previous
#include <cuda_runtime.h>

// ---------------- problem constants ----------------
#define NN 100000
#define VV 3
#define EE 500000
#define EPSL 1e-5f

#define BN 64          // nodes per tile
#define BNP 65         // padded pitch for k-major tiles
#define NT 256         // threads per block
#define NTILES ((NN + BN - 1) / BN)

// ---------------- scratch (device globals; no allocation) ----------------
__device__ float g_pre[(size_t)VV * NN * 128];        // segment-summed weighted features
__device__ float g_wsum[VV * NN];                     // segment-summed edge weights
__device__ float g_selfout[(size_t)NN * 128];
__device__ float g_transformed[(size_t)NN * 128];
__device__ float g_nodeatt[NN];
__device__ float g_viewout[(size_t)VV * NN * 128];
__device__ float g_vscore[VV * NN];

// ---------------- zero scratch ----------------
__global__ void k_zero() {
    size_t tid = (size_t)blockIdx.x * blockDim.x + threadIdx.x;
    size_t stride = (size_t)gridDim.x * blockDim.x;
    size_t total4 = ((size_t)VV * NN * 128) / 4;
    float4 z = make_float4(0.f, 0.f, 0.f, 0.f);
    for (size_t i = tid; i < total4; i += stride)
        reinterpret_cast<float4*>(g_pre)[i] = z;
    for (size_t i = tid; i < (size_t)VV * NN; i += stride)
        g_wsum[i] = 0.f;
}

// ---------------- edge scatter: pre[v,dst] += w * features[src]; wsum += w ----------------
// one warp per edge, vector reductions (16B red ops)
__global__ void __launch_bounds__(NT) k_edge(const int* __restrict__ src,
                                             const int* __restrict__ dst,
                                             const float* __restrict__ w,
                                             const float* __restrict__ feats) {
    int gw = (int)(((size_t)blockIdx.x * NT + threadIdx.x) >> 5);
    if (gw >= VV * EE) return;
    int l = threadIdx.x & 31;
    int v = gw / EE;
    int s = src[gw];
    int d = dst[gw];
    float we = w[gw];
    float4 x = reinterpret_cast<const float4*>(feats + (size_t)s * 128)[l];
    float* p = g_pre + ((size_t)v * NN + d) * 128 + l * 4;
    asm volatile("red.global.add.v4.f32 [%0], {%1,%2,%3,%4};" ::
                 "l"(p), "f"(we * x.x), "f"(we * x.y), "f"(we * x.z), "f"(we * x.w)
                 : "memory");
    if (l == 0) atomicAdd(&g_wsum[v * NN + d], we);
}

// ---------------- shared helpers ----------------
// load 64-node tile of a [*,128] row-major matrix into k-major shared tile Fs[k][n], pitch BNP
__device__ __forceinline__ void load_tileT(const float* __restrict__ g, int nb, float* __restrict__ Fs) {
    int t = threadIdx.x, w = t >> 5, l = t & 31;
#pragma unroll
    for (int r = 0; r < 8; ++r) {
        int grp = r * 8 + w;                 // 0..63
        int i = (grp & 15) * 4 + (l >> 3);   // node 0..63
        int kq = (grp >> 4) * 8 + (l & 7);   // float4 index 0..31
        int n = nb + i;
        float4 v = make_float4(0.f, 0.f, 0.f, 0.f);
        if (n < NN) v = reinterpret_cast<const float4*>(g + (size_t)n * 128)[kq];
        int k = kq * 4;
        Fs[(k + 0) * BNP + i] = v.x;
        Fs[(k + 1) * BNP + i] = v.y;
        Fs[(k + 2) * BNP + i] = v.z;
        Fs[(k + 3) * BNP + i] = v.w;
    }
}

__device__ __forceinline__ void load_w(const float* __restrict__ g, float* __restrict__ Ws, int n4) {
    for (int idx = threadIdx.x; idx < n4; idx += NT)
        reinterpret_cast<float4*>(Ws)[idx] = reinterpret_cast<const float4*>(g)[idx];
}

// register-blocked matmul: acc[4][TN] += Fs[:, ng*4..+3]^T @ Ws[:, cg*TN..]
template <int KDIM, int OC, int TN>
__device__ __forceinline__ void mm_tile(const float* __restrict__ Fs, const float* __restrict__ Ws,
                                        float acc[4][TN], int ng, int cg) {
    const int n0 = ng * 4;
#pragma unroll 8
    for (int k = 0; k < KDIM; ++k) {
        float a0 = Fs[k * BNP + n0 + 0];
        float a1 = Fs[k * BNP + n0 + 1];
        float a2 = Fs[k * BNP + n0 + 2];
        float a3 = Fs[k * BNP + n0 + 3];
        const float4* bp = reinterpret_cast<const float4*>(Ws + k * OC + cg * TN);
        float4 b0 = bp[0];
        if (TN == 8) {
            float4 b1 = bp[1];
            float bv[8] = {b0.x, b0.y, b0.z, b0.w, b1.x, b1.y, b1.z, b1.w};
#pragma unroll
            for (int j = 0; j < 8; ++j) {
                acc[0][j] = fmaf(a0, bv[j], acc[0][j]);
                acc[1][j] = fmaf(a1, bv[j], acc[1][j]);
                acc[2][j] = fmaf(a2, bv[j], acc[2][j]);
                acc[3][j] = fmaf(a3, bv[j], acc[3][j]);
            }
        } else {
            float bv[4] = {b0.x, b0.y, b0.z, b0.w};
#pragma unroll
            for (int j = 0; j < 4; ++j) {
                acc[0][j] = fmaf(a0, bv[j], acc[0][j]);
                acc[1][j] = fmaf(a1, bv[j], acc[1][j]);
                acc[2][j] = fmaf(a2, bv[j], acc[2][j]);
                acc[3][j] = fmaf(a3, bv[j], acc[3][j]);
            }
        }
    }
}

// ---------------- feature-side kernel ----------------
// computes: class_probs -> out_cp, node_att -> g_nodeatt,
//           self_out -> g_selfout, transformed -> g_transformed
__global__ void __launch_bounds__(NT, 2) k_feat(
    const float* __restrict__ feats,
    const float* __restrict__ clsW, const float* __restrict__ clsb,
    const float* __restrict__ attW1, const float* __restrict__ attb1,
    const float* __restrict__ attW2, const float* __restrict__ attb2,
    const float* __restrict__ attbias,
    const float* __restrict__ selfW, const float* __restrict__ selfb,
    const float* __restrict__ featW, const float* __restrict__ featb,
    float* __restrict__ out_cp) {
    extern __shared__ float sm[];
    float* Fs = sm;                  // 128*BNP
    float* Wbuf = Fs + 128 * BNP;    // 16384
    float* clsWs = Wbuf + 16384;     // 256
    float* red = clsWs + 256;        // 16*64
    float* scoreS = red + 1024;      // 128

    int nb = blockIdx.x * BN;
    int ng = threadIdx.x >> 4, cg = threadIdx.x & 15;

    load_tileT(feats, nb, Fs);
    load_w(selfW, Wbuf, 4096);
    load_w(clsW, clsWs, 64);
    __syncthreads();

    float acc[4][8];

    // ---- self_out = f @ selfW + selfb ----
#pragma unroll
    for (int i = 0; i < 4; ++i)
#pragma unroll
        for (int j = 0; j < 8; ++j) acc[i][j] = 0.f;
    mm_tile<128, 128, 8>(Fs, Wbuf, acc, ng, cg);
    {
        float4 sb0 = __ldg(reinterpret_cast<const float4*>(selfb + cg * 8));
        float4 sb1 = __ldg(reinterpret_cast<const float4*>(selfb + cg * 8) + 1);
#pragma unroll
        for (int i = 0; i < 4; ++i) {
            int n = nb + ng * 4 + i;
            if (n < NN) {
                float4 o0 = make_float4(acc[i][0] + sb0.x, acc[i][1] + sb0.y, acc[i][2] + sb0.z, acc[i][3] + sb0.w);
                float4 o1 = make_float4(acc[i][4] + sb1.x, acc[i][5] + sb1.y, acc[i][6] + sb1.z, acc[i][7] + sb1.w);
                float4* o = reinterpret_cast<float4*>(g_selfout + (size_t)n * 128 + cg * 8);
                o[0] = o0; o[1] = o1;
            }
        }
    }
    __syncthreads();
    load_w(featW, Wbuf, 4096);
    __syncthreads();

    // ---- transformed = f @ featW + featb ----
#pragma unroll
    for (int i = 0; i < 4; ++i)
#pragma unroll
        for (int j = 0; j < 8; ++j) acc[i][j] = 0.f;
    mm_tile<128, 128, 8>(Fs, Wbuf, acc, ng, cg);
    {
        float4 fb0 = __ldg(reinterpret_cast<const float4*>(featb + cg * 8));
        float4 fb1 = __ldg(reinterpret_cast<const float4*>(featb + cg * 8) + 1);
#pragma unroll
        for (int i = 0; i < 4; ++i) {
            int n = nb + ng * 4 + i;
            if (n < NN) {
                float4 o0 = make_float4(acc[i][0] + fb0.x, acc[i][1] + fb0.y, acc[i][2] + fb0.z, acc[i][3] + fb0.w);
                float4 o1 = make_float4(acc[i][4] + fb1.x, acc[i][5] + fb1.y, acc[i][6] + fb1.z, acc[i][7] + fb1.w);
                float4* o = reinterpret_cast<float4*>(g_transformed + (size_t)n * 128 + cg * 8);
                o[0] = o0; o[1] = o1;
            }
        }
    }
    __syncthreads();
    // ---- attW1 rearranged: Wbuf[d][c*64+h] = attW1[c][d][h] ----
    for (int idx = threadIdx.x; idx < 2 * 128 * 16; idx += NT) {
        int h4 = idx & 15;
        int d = (idx >> 4) & 127;
        int c = idx >> 11;
        reinterpret_cast<float4*>(Wbuf + d * 128 + c * 64)[h4] =
            __ldg(reinterpret_cast<const float4*>(attW1) + idx);
    }
    __syncthreads();

    // ---- h = relu(f @ attW1 + attb1); partial score dot with attW2 ----
#pragma unroll
    for (int i = 0; i < 4; ++i)
#pragma unroll
        for (int j = 0; j < 8; ++j) acc[i][j] = 0.f;
    mm_tile<128, 128, 8>(Fs, Wbuf, acc, ng, cg);
#pragma unroll
    for (int i = 0; i < 4; ++i) {
        float p = 0.f;
#pragma unroll
        for (int j = 0; j < 8; ++j) {
            int c = cg * 8 + j;   // c = cl*64 + h, attb1/attW2 are flat [C*H]
            float hv = fmaxf(acc[i][j] + __ldg(attb1 + c), 0.f);
            p = fmaf(hv, __ldg(attW2 + c), p);
        }
        red[cg * 64 + ng * 4 + i] = p;
    }
    __syncthreads();
    if (threadIdx.x < 128) {
        int nl = threadIdx.x & 63, cl = threadIdx.x >> 6;
        float s = 0.f;
#pragma unroll
        for (int q = 0; q < 8; ++q) s += red[(cl * 8 + q) * 64 + nl];
        s += __ldg(attb2 + cl);
        scoreS[cl * 64 + nl] = 1.f / (1.f + expf(-s));
    }
    __syncthreads();
    if (threadIdx.x < 64) {
        int nl = threadIdx.x, n = nb + nl;
        if (n < NN) {
            float l0 = __ldg(clsb), l1 = __ldg(clsb + 1);
            for (int k = 0; k < 128; ++k) {
                float f = Fs[k * BNP + nl];
                l0 = fmaf(f, clsWs[k * 2], l0);
                l1 = fmaf(f, clsWs[k * 2 + 1], l1);
            }
            float m = fmaxf(l0, l1);
            float e0 = expf(l0 - m), e1 = expf(l1 - m);
            float inv = 1.f / (e0 + e1);
            float cp0 = e0 * inv, cp1 = e1 * inv;
            out_cp[(size_t)n * 2] = cp0;
            out_cp[(size_t)n * 2 + 1] = cp1;
            g_nodeatt[n] = scoreS[nl] * cp0 + scoreS[64 + nl] * cp1 + __ldg(attbias);
        }
    }
}

// ---------------- per-view kernel ----------------
// agg = pre@relW + wsum*relb ; gate = sigmoid(agg@gateW + gateb) ; view_out = gate*agg
// vscore = relu((view_out*view_pref)@vattW1 + vattb1) . vattW2 + vattb2
__global__ void __launch_bounds__(NT, 2) k_view(
    const float* __restrict__ relW, const float* __restrict__ relb,
    const float* __restrict__ gateW, const float* __restrict__ gateb,
    const float* __restrict__ view_pref,
    const float* __restrict__ vattW1, const float* __restrict__ vattb1,
    const float* __restrict__ vattW2, const float* __restrict__ vattb2) {
    extern __shared__ float sm[];
    float* buf = sm;                 // 128*BNP  (Ps -> As -> VOs)
    float* Wbuf = buf + 128 * BNP;   // 16384
    float* wsumS = Wbuf + 16384;     // 64
    float* red = wsumS + 64;         // 1024

    int v = blockIdx.y;
    int nb = blockIdx.x * BN;
    int ng = threadIdx.x >> 4, cg = threadIdx.x & 15;

    load_tileT(g_pre + (size_t)v * NN * 128, nb, buf);
    load_w(relW + (size_t)v * 16384, Wbuf, 4096);
    if (threadIdx.x < 64) {
        int n = nb + threadIdx.x;
        wsumS[threadIdx.x] = (n < NN) ? g_wsum[v * NN + n] : 0.f;
    }
    __syncthreads();

    // ---- agg ----
    float acc[4][8];
#pragma unroll
    for (int i = 0; i < 4; ++i)
#pragma unroll
        for (int j = 0; j < 8; ++j) acc[i][j] = 0.f;
    mm_tile<128, 128, 8>(buf, Wbuf, acc, ng, cg);
    {
        float4 rb0 = __ldg(reinterpret_cast<const float4*>(relb + v * 128 + cg * 8));
        float4 rb1 = __ldg(reinterpret_cast<const float4*>(relb + v * 128 + cg * 8) + 1);
        float rb[8] = {rb0.x, rb0.y, rb0.z, rb0.w, rb1.x, rb1.y, rb1.z, rb1.w};
#pragma unroll
        for (int i = 0; i < 4; ++i) {
            float ws = wsumS[ng * 4 + i];
#pragma unroll
            for (int j = 0; j < 8; ++j) acc[i][j] = fmaf(ws, rb[j], acc[i][j]);
        }
    }
    __syncthreads();   // all threads done reading Ps + relW
    // stash agg tile k-major for the gate matmul
#pragma unroll
    for (int i = 0; i < 4; ++i)
#pragma unroll
        for (int j = 0; j < 8; ++j)
            buf[(cg * 8 + j) * BNP + ng * 4 + i] = acc[i][j];
    load_w(gateW + (size_t)v * 16384, Wbuf, 4096);
    __syncthreads();

    // ---- gate, view_out ----
    float gac[4][8];
#pragma unroll
    for (int i = 0; i < 4; ++i)
#pragma unroll
        for (int j = 0; j < 8; ++j) gac[i][j] = 0.f;
    mm_tile<128, 128, 8>(buf, Wbuf, gac, ng, cg);
    {
        float4 gb0 = __ldg(reinterpret_cast<const float4*>(gateb + v * 128 + cg * 8));
        float4 gb1 = __ldg(reinterpret_cast<const float4*>(gateb + v * 128 + cg * 8) + 1);
        float gb[8] = {gb0.x, gb0.y, gb0.z, gb0.w, gb1.x, gb1.y, gb1.z, gb1.w};
#pragma unroll
        for (int i = 0; i < 4; ++i)
#pragma unroll
            for (int j = 0; j < 8; ++j) {
                float gate = 1.f / (1.f + expf(-(gac[i][j] + gb[j])));
                gac[i][j] = gate * acc[i][j];   // gac now holds view_out
            }
    }
#pragma unroll
    for (int i = 0; i < 4; ++i) {
        int n = nb + ng * 4 + i;
        if (n < NN) {
            float4* o = reinterpret_cast<float4*>(g_viewout + ((size_t)v * NN + n) * 128 + cg * 8);
            o[0] = make_float4(gac[i][0], gac[i][1], gac[i][2], gac[i][3]);
            o[1] = make_float4(gac[i][4], gac[i][5], gac[i][6], gac[i][7]);
        }
    }
    __syncthreads();   // all threads done reading As + gateW
    // stash view_out * view_pref for the view-attention matmul
    {
        float4 vp0 = __ldg(reinterpret_cast<const float4*>(view_pref + v * 128 + cg * 8));
        float4 vp1 = __ldg(reinterpret_cast<const float4*>(view_pref + v * 128 + cg * 8) + 1);
        float vp[8] = {vp0.x, vp0.y, vp0.z, vp0.w, vp1.x, vp1.y, vp1.z, vp1.w};
#pragma unroll
        for (int i = 0; i < 4; ++i)
#pragma unroll
            for (int j = 0; j < 8; ++j)
                buf[(cg * 8 + j) * BNP + ng * 4 + i] = gac[i][j] * vp[j];
    }
    load_w(vattW1, Wbuf, 2048);
    __syncthreads();

    // ---- view-attention score ----
    float vac[4][4];
#pragma unroll
    for (int i = 0; i < 4; ++i)
#pragma unroll
        for (int j = 0; j < 4; ++j) vac[i][j] = 0.f;
    mm_tile<128, 64, 4>(buf, Wbuf, vac, ng, cg);
    {
        float4 vb = __ldg(reinterpret_cast<const float4*>(vattb1 + cg * 4));
        float4 vw = __ldg(reinterpret_cast<const float4*>(vattW2 + cg * 4));
        float vbb[4] = {vb.x, vb.y, vb.z, vb.w};
        float vww[4] = {vw.x, vw.y, vw.z, vw.w};
#pragma unroll
        for (int i = 0; i < 4; ++i) {
            float s = 0.f;
#pragma unroll
            for (int j = 0; j < 4; ++j) {
                float vh = fmaxf(vac[i][j] + vbb[j], 0.f);
                s = fmaf(vh, vww[j], s);
            }
            red[cg * 64 + ng * 4 + i] = s;
        }
    }
    __syncthreads();
    if (threadIdx.x < 64) {
        int nl = threadIdx.x, n = nb + nl;
        if (n < NN) {
            float s = __ldg(vattb2);
#pragma unroll
            for (int q = 0; q < 16; ++q) s += red[q * 64 + nl];
            g_vscore[v * NN + n] = s;
        }
    }
}

// ---------------- fusion + residual + layer norm ----------------
__global__ void __launch_bounds__(NT, 1) k_fuse(
    const float* __restrict__ fusW, const float* __restrict__ fusb,
    const float* __restrict__ ln_g, const float* __restrict__ ln_b,
    float* __restrict__ out) {
    extern __shared__ float sm[];
    float* Zs = sm;                  // 256*BNP
    float* Wf = Zs + 256 * BNP;      // 32768
    float* vwA = Wf + 32768;         // 3*64 (view weight * node_att)
    float* redA = vwA + 192;         // 1024
    float* redB = redA + 1024;       // 1024
    float* muS = redB + 1024;        // 64
    float* rsS = muS + 64;           // 64

    int nb = blockIdx.x * BN;
    int ng = threadIdx.x >> 4, cg = threadIdx.x & 15;

    if (threadIdx.x < 64) {
        int nl = threadIdx.x, n = nb + nl;
        float s0 = 0.f, s1 = 0.f, s2 = 0.f, na = 0.f;
        if (n < NN) {
            s0 = g_vscore[n];
            s1 = g_vscore[NN + n];
            s2 = g_vscore[2 * NN + n];
            na = g_nodeatt[n];
        }
        float m = fmaxf(s0, fmaxf(s1, s2));
        float e0 = expf(s0 - m), e1 = expf(s1 - m), e2 = expf(s2 - m);
        float inv = na / (e0 + e1 + e2);
        vwA[nl] = e0 * inv;
        vwA[64 + nl] = e1 * inv;
        vwA[128 + nl] = e2 * inv;
    }
    load_w(fusW, Wf, 8192);
    __syncthreads();

    // rows 0..127: self_out
    load_tileT(g_selfout, nb, Zs);
    // rows 128..255: weighted = (sum_v vw*view_out) * node_att
    {
        int t = threadIdx.x, w = t >> 5, l = t & 31;
#pragma unroll
        for (int r = 0; r < 8; ++r) {
            int grp = r * 8 + w;
            int i = (grp & 15) * 4 + (l >> 3);
            int kq = (grp >> 4) * 8 + (l & 7);
            int n = nb + i;
            float4 a = make_float4(0.f, 0.f, 0.f, 0.f);
            if (n < NN) {
                float w0 = vwA[i], w1 = vwA[64 + i], w2 = vwA[128 + i];
                float4 x0 = reinterpret_cast<const float4*>(g_viewout + (size_t)n * 128)[kq];
                float4 x1 = reinterpret_cast<const float4*>(g_viewout + ((size_t)NN + n) * 128)[kq];
                float4 x2 = reinterpret_cast<const float4*>(g_viewout + ((size_t)2 * NN + n) * 128)[kq];
                a.x = w0 * x0.x + w1 * x1.x + w2 * x2.x;
                a.y = w0 * x0.y + w1 * x1.y + w2 * x2.y;
                a.z = w0 * x0.z + w1 * x1.z + w2 * x2.z;
                a.w = w0 * x0.w + w1 * x1.w + w2 * x2.w;
            }
            int k = 128 + kq * 4;
            Zs[(k + 0) * BNP + i] = a.x;
            Zs[(k + 1) * BNP + i] = a.y;
            Zs[(k + 2) * BNP + i] = a.z;
            Zs[(k + 3) * BNP + i] = a.w;
        }
    }
    __syncthreads();

    float acc[4][8];
#pragma unroll
    for (int i = 0; i < 4; ++i)
#pragma unroll
        for (int j = 0; j < 8; ++j) acc[i][j] = 0.f;
    mm_tile<256, 128, 8>(Zs, Wf, acc, ng, cg);

    {
        float4 fb0 = __ldg(reinterpret_cast<const float4*>(fusb + cg * 8));
        float4 fb1 = __ldg(reinterpret_cast<const float4*>(fusb + cg * 8) + 1);
        float fb[8] = {fb0.x, fb0.y, fb0.z, fb0.w, fb1.x, fb1.y, fb1.z, fb1.w};
#pragma unroll
        for (int i = 0; i < 4; ++i) {
            int n = nb + ng * 4 + i;
            float tr[8] = {0.f, 0.f, 0.f, 0.f, 0.f, 0.f, 0.f, 0.f};
            if (n < NN) {
                float4 t0 = reinterpret_cast<const float4*>(g_transformed + (size_t)n * 128 + cg * 8)[0];
                float4 t1 = reinterpret_cast<const float4*>(g_transformed + (size_t)n * 128 + cg * 8)[1];
                tr[0] = t0.x; tr[1] = t0.y; tr[2] = t0.z; tr[3] = t0.w;
                tr[4] = t1.x; tr[5] = t1.y; tr[6] = t1.z; tr[7] = t1.w;
            }
            float s = 0.f, s2 = 0.f;
#pragma unroll
            for (int j = 0; j < 8; ++j) {
                float f = fmaxf(acc[i][j] + fb[j], 0.f) + tr[j];
                acc[i][j] = f;
                s += f;
                s2 = fmaf(f, f, s2);
            }
            redA[cg * 64 + ng * 4 + i] = s;
            redB[cg * 64 + ng * 4 + i] = s2;
        }
    }
    __syncthreads();
    if (threadIdx.x < 64) {
        int nl = threadIdx.x;
        float sa = 0.f, sb = 0.f;
#pragma unroll
        for (int q = 0; q < 16; ++q) {
            sa += redA[q * 64 + nl];
            sb += redB[q * 64 + nl];
        }
        float mu = sa * (1.f / 128.f);
        float var = sb * (1.f / 128.f) - mu * mu;
        muS[nl] = mu;
        rsS[nl] = rsqrtf(var + EPSL);
    }
    __syncthreads();
    {
        float4 lg0 = __ldg(reinterpret_cast<const float4*>(ln_g + cg * 8));
        float4 lg1 = __ldg(reinterpret_cast<const float4*>(ln_g + cg * 8) + 1);
        float4 lb0 = __ldg(reinterpret_cast<const float4*>(ln_b + cg * 8));
        float4 lb1 = __ldg(reinterpret_cast<const float4*>(ln_b + cg * 8) + 1);
        float lg[8] = {lg0.x, lg0.y, lg0.z, lg0.w, lg1.x, lg1.y, lg1.z, lg1.w};
        float lb[8] = {lb0.x, lb0.y, lb0.z, lb0.w, lb1.x, lb1.y, lb1.z, lb1.w};
#pragma unroll
        for (int i = 0; i < 4; ++i) {
            int nl = ng * 4 + i;
            int n = nb + nl;
            if (n < NN) {
                float mu = muS[nl], rs = rsS[nl];
                float o[8];
#pragma unroll
                for (int j = 0; j < 8; ++j)
                    o[j] = (acc[i][j] - mu) * rs * lg[j] + lb[j];
                float4* op = reinterpret_cast<float4*>(out + (size_t)n * 128 + cg * 8);
                op[0] = make_float4(o[0], o[1], o[2], o[3]);
                op[1] = make_float4(o[4], o[5], o[6], o[7]);
            }
        }
    }
}

// ---------------- launch ----------------
extern "C" void kernel_launch(void* const* d_in, const int* in_sizes, int n_in,
                              void* d_out, int out_size) {
    const float* feats   = (const float*)d_in[0];
    const int*   esrc    = (const int*)d_in[1];
    const int*   edst    = (const int*)d_in[2];
    const float* ew      = (const float*)d_in[3];
    const float* clsW    = (const float*)d_in[4];
    const float* clsb    = (const float*)d_in[5];
    const float* attW1   = (const float*)d_in[6];
    const float* attb1   = (const float*)d_in[7];
    const float* attW2   = (const float*)d_in[8];
    const float* attb2   = (const float*)d_in[9];
    const float* attbias = (const float*)d_in[10];
    const float* relW    = (const float*)d_in[11];
    const float* relb    = (const float*)d_in[12];
    const float* gateW   = (const float*)d_in[13];
    const float* gateb   = (const float*)d_in[14];
    const float* vpref   = (const float*)d_in[15];
    const float* vattW1  = (const float*)d_in[16];
    const float* vattb1  = (const float*)d_in[17];
    const float* vattW2  = (const float*)d_in[18];
    const float* vattb2  = (const float*)d_in[19];
    const float* selfW   = (const float*)d_in[20];
    const float* selfb   = (const float*)d_in[21];
    const float* featW   = (const float*)d_in[22];
    const float* featb   = (const float*)d_in[23];
    const float* fusW    = (const float*)d_in[24];
    const float* fusb    = (const float*)d_in[25];
    const float* lng     = (const float*)d_in[26];
    const float* lnb     = (const float*)d_in[27];

    float* out = (float*)d_out;
    float* out_cp = out + (size_t)NN * 128;

    const int SMEM_FEAT = (128 * BNP + 16384 + 256 + 1024 + 128) * 4;
    const int SMEM_VIEW = (128 * BNP + 16384 + 64 + 1024) * 4;
    const int SMEM_FUSE = (256 * BNP + 32768 + 192 + 1024 + 1024 + 64 + 64) * 4;

    cudaFuncSetAttribute(k_feat, cudaFuncAttributeMaxDynamicSharedMemorySize, SMEM_FEAT);
    cudaFuncSetAttribute(k_view, cudaFuncAttributeMaxDynamicSharedMemorySize, SMEM_VIEW);
    cudaFuncSetAttribute(k_fuse, cudaFuncAttributeMaxDynamicSharedMemorySize, SMEM_FUSE);

    k_zero<<<2048, NT>>>();

    {
        long long warps = (long long)VV * EE;
        int blocks = (int)((warps * 32 + NT - 1) / NT);
        k_edge<<<blocks, NT>>>(esrc, edst, ew, feats);
    }

    k_feat<<<NTILES, NT, SMEM_FEAT>>>(feats, clsW, clsb, attW1, attb1, attW2, attb2,
                                      attbias, selfW, selfb, featW, featb, out_cp);

    dim3 gv(NTILES, VV);
    k_view<<<gv, NT, SMEM_VIEW>>>(relW, relb, gateW, gateb, vpref,
                                  vattW1, vattb1, vattW2, vattb2);

    k_fuse<<<NTILES, NT, SMEM_FUSE>>>(fusW, fusb, lng, lnb, out);
}

// round 4
// speedup vs baseline: 1.3659x; 1.3645x over previous
#include <cuda_runtime.h>
#include <cstdint>

// ---------------- problem constants ----------------
#define NN 100000
#define VV 3
#define EE 500000
#define EPSL 1e-5f

#define BN 128         // nodes per tile
#define NT 256         // threads per block
#define NTILES ((NN + BN - 1) / BN)   // 782

typedef unsigned long long ull;

// ---------------- scratch (device globals; no allocation) ----------------
__device__ float g_pre[(size_t)VV * NN * 128];
__device__ float g_wsum[VV * NN];
__device__ float g_selfout[(size_t)NN * 128];
__device__ float g_transformed[(size_t)NN * 128];
__device__ float g_nodeatt[NN];
__device__ float g_viewout[(size_t)VV * NN * 128];
__device__ float g_vscore[VV * NN];

// ---------------- small helpers ----------------
__device__ __forceinline__ void ffma2(ull &d, ull a, ull b) {
    asm("fma.rn.f32x2 %0, %1, %2, %0;" : "+l"(d) : "l"(a), "l"(b));
}
__device__ __forceinline__ ull fdup(float a) {
    ull r; asm("mov.b64 %0, {%1, %1};" : "=l"(r) : "f"(a)); return r;
}
__device__ __forceinline__ float2 u2f(ull v) {
    float2 r; asm("mov.b64 {%0, %1}, %2;" : "=f"(r.x), "=f"(r.y) : "l"(v)); return r;
}
__device__ __forceinline__ float sigm(float x) { return 1.f / (1.f + __expf(-x)); }

__device__ __forceinline__ unsigned smaddr(const void* p) {
    unsigned r;
    asm("{ .reg .u64 t; cvta.to.shared.u64 t, %1; cvt.u32.u64 %0, t; }" : "=r"(r) : "l"(p));
    return r;
}
#define MBAR_INIT(a) asm volatile("mbarrier.init.shared.b64 [%0], 1;" :: "r"(a))
#define MBAR_EXPECT(a, bytes) \
    asm volatile("mbarrier.arrive.expect_tx.shared.b64 _, [%0], %1;" :: "r"(a), "r"(bytes))
#define MBAR_WAIT(a, parity) do { \
    unsigned _p = 0; \
    while (!_p) { \
        asm volatile("{\n\t.reg .pred P;\n\t" \
                     "mbarrier.try_wait.parity.shared.b64 P, [%1], %2, 0x989680;\n\t" \
                     "selp.u32 %0, 1, 0, P;\n\t}" \
                     : "=r"(_p) : "r"(a), "r"((unsigned)(parity))); \
    } } while (0)

__device__ __forceinline__ void bulk_g2s(unsigned dst, const void* src, unsigned bytes, unsigned mbar) {
    asm volatile("cp.async.bulk.shared::cluster.global.mbarrier::complete_tx::bytes [%0], [%1], %2, [%3];"
                 :: "r"(dst), "l"(src), "r"(bytes), "r"(mbar) : "memory");
}

// ---------------- zero scratch ----------------
__global__ void k_zero() {
    size_t tid = (size_t)blockIdx.x * blockDim.x + threadIdx.x;
    size_t stride = (size_t)gridDim.x * blockDim.x;
    size_t total4 = ((size_t)VV * NN * 128) / 4;
    float4 z = make_float4(0.f, 0.f, 0.f, 0.f);
    for (size_t i = tid; i < total4; i += stride)
        reinterpret_cast<float4*>(g_pre)[i] = z;
    for (size_t i = tid; i < (size_t)VV * NN; i += stride)
        g_wsum[i] = 0.f;
}

// ---------------- edge scatter ----------------
__global__ void __launch_bounds__(NT) k_edge(const int* __restrict__ src,
                                             const int* __restrict__ dst,
                                             const float* __restrict__ w,
                                             const float* __restrict__ feats) {
    int gw = (int)(((size_t)blockIdx.x * NT + threadIdx.x) >> 5);
    if (gw >= VV * EE) return;
    int l = threadIdx.x & 31;
    int v = gw / EE;
    int s = src[gw];
    int d = dst[gw];
    float we = w[gw];
    float4 x = reinterpret_cast<const float4*>(feats + (size_t)s * 128)[l];
    float* p = g_pre + ((size_t)v * NN + d) * 128 + l * 4;
    asm volatile("red.global.add.v4.f32 [%0], {%1,%2,%3,%4};" ::
                 "l"(p), "f"(we * x.x), "f"(we * x.y), "f"(we * x.z), "f"(we * x.w)
                 : "memory");
    if (l == 0) atomicAdd(&g_wsum[v * NN + d], we);
}

// ---------------- tile loaders ----------------
__device__ __forceinline__ void load_tile_rm(const float* __restrict__ g, int nb,
                                             float* __restrict__ Fs) {
    int t = threadIdx.x;
#pragma unroll
    for (int r = 0; r < 16; ++r) {
        int idx = r * NT + t;          // 0..4095 float4s
        int n = idx >> 5;              // 0..127
        int kq = idx & 31;
        float4 v = make_float4(0.f, 0.f, 0.f, 0.f);
        if (nb + n < NN) v = reinterpret_cast<const float4*>(g + (size_t)(nb + n) * 128)[kq];
        reinterpret_cast<float4*>(Fs + n * 128)[kq] = v;
    }
}

// ---------------- 8x8 register-blocked matmul with FFMA2 ----------------
// Fs row-major [128][128]; wbase points at this thread's first output column of
// the B matrix, row stride BSTRIDE floats. acc2[i][j] = packed cols (2j, 2j+1).
template <int KDIM, int BSTRIDE>
__device__ __forceinline__ void mm8x8(const float* __restrict__ Fs, const float* __restrict__ wbase,
                                      ull acc2[8][4], int n0) {
#pragma unroll 4
    for (int kk = 0; kk < KDIM; kk += 2) {
        float2 a2[8];
#pragma unroll
        for (int i = 0; i < 8; ++i)
            a2[i] = *reinterpret_cast<const float2*>(Fs + (n0 + i) * 128 + kk);
#pragma unroll
        for (int q = 0; q < 2; ++q) {
            const float* wrow = wbase + (kk + q) * BSTRIDE;
            ulonglong2 b01 = *reinterpret_cast<const ulonglong2*>(wrow);
            ulonglong2 b23 = *reinterpret_cast<const ulonglong2*>(wrow + 4);
#pragma unroll
            for (int i = 0; i < 8; ++i) {
                ull ad = fdup(q == 0 ? a2[i].x : a2[i].y);
                ffma2(acc2[i][0], ad, b01.x);
                ffma2(acc2[i][1], ad, b01.y);
                ffma2(acc2[i][2], ad, b23.x);
                ffma2(acc2[i][3], ad, b23.y);
            }
        }
    }
}

// 8x4 variant (OC=64, view attention)
__device__ __forceinline__ void mm8x4_64(const float* __restrict__ Fs, const float* __restrict__ wbase,
                                         ull acc2[8][2], int n0) {
#pragma unroll 4
    for (int kk = 0; kk < 128; kk += 2) {
        float2 a2[8];
#pragma unroll
        for (int i = 0; i < 8; ++i)
            a2[i] = *reinterpret_cast<const float2*>(Fs + (n0 + i) * 128 + kk);
#pragma unroll
        for (int q = 0; q < 2; ++q) {
            ulonglong2 b01 = *reinterpret_cast<const ulonglong2*>(wbase + (kk + q) * 64);
#pragma unroll
            for (int i = 0; i < 8; ++i) {
                ull ad = fdup(q == 0 ? a2[i].x : a2[i].y);
                ffma2(acc2[i][0], ad, b01.x);
                ffma2(acc2[i][1], ad, b01.y);
            }
        }
    }
}

#define ZERO_ACC8x8(acc2) do { \
    _Pragma("unroll") for (int i = 0; i < 8; ++i) \
    _Pragma("unroll") for (int j = 0; j < 4; ++j) acc2[i][j] = 0ull; } while (0)

// ---------------- feature-side kernel ----------------
// smem layout (floats): [0:4) mbars | Fs 16384 | W0 16384 | W1 16384 | clsWs 256 | red 2048 | scoreS 256
__global__ void __launch_bounds__(NT, 1) k_feat(
    const float* __restrict__ feats,
    const float* __restrict__ clsW, const float* __restrict__ clsb,
    const float* __restrict__ attW1, const float* __restrict__ attb1,
    const float* __restrict__ attW2, const float* __restrict__ attb2,
    const float* __restrict__ attbias,
    const float* __restrict__ selfW, const float* __restrict__ selfb,
    const float* __restrict__ featW, const float* __restrict__ featb,
    float* __restrict__ out_cp) {
    extern __shared__ float sm[];
    float* Fs = sm + 4;
    float* W0 = Fs + 16384;
    float* W1 = W0 + 16384;
    float* clsWs = W1 + 16384;
    float* red = clsWs + 256;
    float* scoreS = red + 2048;
    unsigned mb0 = smaddr(sm), mb1 = mb0 + 8;

    int nb = blockIdx.x * BN;
    int t = threadIdx.x;
    int ng = t >> 4, cg = t & 15;
    int n0 = ng * 8, c0 = cg * 8;

    if (t == 0) { MBAR_INIT(mb0); MBAR_INIT(mb1); }
    __syncthreads();
    if (t == 0) {
        MBAR_EXPECT(mb0, 65536u);
        bulk_g2s(smaddr(W0), selfW, 65536u, mb0);
        MBAR_EXPECT(mb1, 65536u);
        bulk_g2s(smaddr(W1), featW, 65536u, mb1);
    }
    load_tile_rm(feats, nb, Fs);
    if (t < 64)
        reinterpret_cast<float4*>(clsWs)[t] = __ldg(reinterpret_cast<const float4*>(clsW) + t);
    __syncthreads();

    ull acc2[8][4];

    // ---- self_out = f @ selfW + selfb ----
    MBAR_WAIT(mb0, 0);
    ZERO_ACC8x8(acc2);
    mm8x8<128, 128>(Fs, W0 + c0, acc2, n0);
    {
        float4 b0 = __ldg(reinterpret_cast<const float4*>(selfb + c0));
        float4 b1 = __ldg(reinterpret_cast<const float4*>(selfb + c0) + 1);
#pragma unroll
        for (int i = 0; i < 8; ++i) {
            int n = nb + n0 + i;
            if (n < NN) {
                float2 p0 = u2f(acc2[i][0]), p1 = u2f(acc2[i][1]);
                float2 p2 = u2f(acc2[i][2]), p3 = u2f(acc2[i][3]);
                float4* o = reinterpret_cast<float4*>(g_selfout + (size_t)n * 128 + c0);
                o[0] = make_float4(p0.x + b0.x, p0.y + b0.y, p1.x + b0.z, p1.y + b0.w);
                o[1] = make_float4(p2.x + b1.x, p2.y + b1.y, p3.x + b1.z, p3.y + b1.w);
            }
        }
    }
    __syncthreads();   // everyone done reading W0
    if (t == 0) {
        MBAR_EXPECT(mb0, 65536u);
        bulk_g2s(smaddr(W0), attW1, 65536u, mb0);   // attW1 is [2][128][64] = 16384 floats
    }

    // ---- transformed = f @ featW + featb ----
    MBAR_WAIT(mb1, 0);
    ZERO_ACC8x8(acc2);
    mm8x8<128, 128>(Fs, W1 + c0, acc2, n0);
    {
        float4 b0 = __ldg(reinterpret_cast<const float4*>(featb + c0));
        float4 b1 = __ldg(reinterpret_cast<const float4*>(featb + c0) + 1);
#pragma unroll
        for (int i = 0; i < 8; ++i) {
            int n = nb + n0 + i;
            if (n < NN) {
                float2 p0 = u2f(acc2[i][0]), p1 = u2f(acc2[i][1]);
                float2 p2 = u2f(acc2[i][2]), p3 = u2f(acc2[i][3]);
                float4* o = reinterpret_cast<float4*>(g_transformed + (size_t)n * 128 + c0);
                o[0] = make_float4(p0.x + b0.x, p0.y + b0.y, p1.x + b0.z, p1.y + b0.w);
                o[1] = make_float4(p2.x + b1.x, p2.y + b1.y, p3.x + b1.z, p3.y + b1.w);
            }
        }
    }

    // ---- label attention hidden + partial scores ----
    // native attW1 layout [c][d][h]: column (c*64+h) at row d lives at c*8192 + d*64 + h
    MBAR_WAIT(mb0, 1);
    ZERO_ACC8x8(acc2);
    mm8x8<128, 64>(Fs, W0 + (c0 >> 6) * 8192 + (c0 & 63), acc2, n0);
#pragma unroll
    for (int i = 0; i < 8; ++i) {
        float p = 0.f;
#pragma unroll
        for (int jp = 0; jp < 4; ++jp) {
            float2 f2 = u2f(acc2[i][jp]);
            int col = c0 + 2 * jp;
            float h0 = fmaxf(f2.x + __ldg(attb1 + col), 0.f);
            float h1 = fmaxf(f2.y + __ldg(attb1 + col + 1), 0.f);
            p = fmaf(h0, __ldg(attW2 + col), p);
            p = fmaf(h1, __ldg(attW2 + col + 1), p);
        }
        red[cg * 128 + n0 + i] = p;
    }
    __syncthreads();
    {
        int c = t >> 7, n = t & 127;
        float s = __ldg(attb2 + c);
#pragma unroll
        for (int q = 0; q < 8; ++q) s += red[(c * 8 + q) * 128 + n];
        scoreS[c * 128 + n] = sigm(s);
    }
    __syncthreads();
    if (t < 128) {
        int nl = t, n = nb + nl;
        if (n < NN) {
            float l0 = __ldg(clsb), l1 = __ldg(clsb + 1);
#pragma unroll 8
            for (int q = 0; q < 32; ++q) {
                int kq = (q + nl) & 31;
                float4 f = reinterpret_cast<const float4*>(Fs + nl * 128)[kq];
                const float* cw = clsWs + kq * 8;
                l0 = fmaf(f.x, cw[0], l0); l1 = fmaf(f.x, cw[1], l1);
                l0 = fmaf(f.y, cw[2], l0); l1 = fmaf(f.y, cw[3], l1);
                l0 = fmaf(f.z, cw[4], l0); l1 = fmaf(f.z, cw[5], l1);
                l0 = fmaf(f.w, cw[6], l0); l1 = fmaf(f.w, cw[7], l1);
            }
            float m = fmaxf(l0, l1);
            float e0 = __expf(l0 - m), e1 = __expf(l1 - m);
            float inv = 1.f / (e0 + e1);
            float cp0 = e0 * inv, cp1 = e1 * inv;
            out_cp[(size_t)n * 2] = cp0;
            out_cp[(size_t)n * 2 + 1] = cp1;
            g_nodeatt[n] = scoreS[nl] * cp0 + scoreS[128 + nl] * cp1 + __ldg(attbias);
        }
    }
}

// ---------------- per-view kernel ----------------
// smem layout: [0:4) mbars | Fs 16384 | W0 16384 | W1 16384 | wsumS 128 | red 2048
__global__ void __launch_bounds__(NT, 1) k_view(
    const float* __restrict__ relW, const float* __restrict__ relb,
    const float* __restrict__ gateW, const float* __restrict__ gateb,
    const float* __restrict__ view_pref,
    const float* __restrict__ vattW1, const float* __restrict__ vattb1,
    const float* __restrict__ vattW2, const float* __restrict__ vattb2) {
    extern __shared__ float sm[];
    float* Fs = sm + 4;
    float* W0 = Fs + 16384;
    float* W1 = W0 + 16384;
    float* wsumS = W1 + 16384;
    float* red = wsumS + 128;
    unsigned mb0 = smaddr(sm), mb1 = mb0 + 8;

    int v = blockIdx.y;
    int nb = blockIdx.x * BN;
    int t = threadIdx.x;
    int ng = t >> 4, cg = t & 15;
    int n0 = ng * 8, c0 = cg * 8;

    if (t == 0) { MBAR_INIT(mb0); MBAR_INIT(mb1); }
    __syncthreads();
    if (t == 0) {
        MBAR_EXPECT(mb0, 65536u);
        bulk_g2s(smaddr(W0), relW + (size_t)v * 16384, 65536u, mb0);
        MBAR_EXPECT(mb1, 65536u);
        bulk_g2s(smaddr(W1), gateW + (size_t)v * 16384, 65536u, mb1);
    }
    load_tile_rm(g_pre + (size_t)v * NN * 128, nb, Fs);
    if (t < 128) {
        int n = nb + t;
        wsumS[t] = (n < NN) ? g_wsum[v * NN + n] : 0.f;
    }
    __syncthreads();

    // ---- agg = pre @ relW + wsum * relb ----
    ull acc2[8][4];
    MBAR_WAIT(mb0, 0);
    ZERO_ACC8x8(acc2);
    mm8x8<128, 128>(Fs, W0 + c0, acc2, n0);
    {
        ulonglong2 r01 = __ldg(reinterpret_cast<const ulonglong2*>(relb + v * 128 + c0));
        ulonglong2 r23 = __ldg(reinterpret_cast<const ulonglong2*>(relb + v * 128 + c0) + 1);
#pragma unroll
        for (int i = 0; i < 8; ++i) {
            ull wd = fdup(wsumS[n0 + i]);
            ffma2(acc2[i][0], wd, r01.x);
            ffma2(acc2[i][1], wd, r01.y);
            ffma2(acc2[i][2], wd, r23.x);
            ffma2(acc2[i][3], wd, r23.y);
        }
    }
    __syncthreads();   // everyone done reading Fs(pre) + W0(relW)
    if (t == 0) {
        MBAR_EXPECT(mb0, 32768u);
        bulk_g2s(smaddr(W0), vattW1, 32768u, mb0);   // [128][64] = 8192 floats
    }
    // stash agg row-major into Fs (own 8x8 block)
#pragma unroll
    for (int i = 0; i < 8; ++i) {
        float2 p0 = u2f(acc2[i][0]), p1 = u2f(acc2[i][1]);
        float2 p2 = u2f(acc2[i][2]), p3 = u2f(acc2[i][3]);
        float4* o = reinterpret_cast<float4*>(Fs + (n0 + i) * 128 + c0);
        o[0] = make_float4(p0.x, p0.y, p1.x, p1.y);
        o[1] = make_float4(p2.x, p2.y, p3.x, p3.y);
    }
    __syncthreads();   // agg tile ready

    // ---- gate matmul ----
    ull gac2[8][4];
    MBAR_WAIT(mb1, 0);
#pragma unroll
    for (int i = 0; i < 8; ++i)
#pragma unroll
        for (int j = 0; j < 4; ++j) gac2[i][j] = 0ull;
    mm8x8<128, 128>(Fs, W1 + c0, gac2, n0);

    float vo[8][8];
    {
        float4 gb0 = __ldg(reinterpret_cast<const float4*>(gateb + v * 128 + c0));
        float4 gb1 = __ldg(reinterpret_cast<const float4*>(gateb + v * 128 + c0) + 1);
        float gb[8] = {gb0.x, gb0.y, gb0.z, gb0.w, gb1.x, gb1.y, gb1.z, gb1.w};
#pragma unroll
        for (int i = 0; i < 8; ++i) {
            const float4* ap = reinterpret_cast<const float4*>(Fs + (n0 + i) * 128 + c0);
            float4 a0 = ap[0], a1 = ap[1];
            float ag[8] = {a0.x, a0.y, a0.z, a0.w, a1.x, a1.y, a1.z, a1.w};
            float gl[8];
#pragma unroll
            for (int jp = 0; jp < 4; ++jp) {
                float2 f2 = u2f(gac2[i][jp]);
                gl[2 * jp] = f2.x; gl[2 * jp + 1] = f2.y;
            }
#pragma unroll
            for (int j = 0; j < 8; ++j)
                vo[i][j] = sigm(gl[j] + gb[j]) * ag[j];
        }
    }
    __syncthreads();   // everyone done reading Fs(agg) + W1(gateW)
    {
        float4 vp0 = __ldg(reinterpret_cast<const float4*>(view_pref + v * 128 + c0));
        float4 vp1 = __ldg(reinterpret_cast<const float4*>(view_pref + v * 128 + c0) + 1);
        float vp[8] = {vp0.x, vp0.y, vp0.z, vp0.w, vp1.x, vp1.y, vp1.z, vp1.w};
#pragma unroll
        for (int i = 0; i < 8; ++i) {
            int n = nb + n0 + i;
            if (n < NN) {
                float4* o = reinterpret_cast<float4*>(g_viewout + ((size_t)v * NN + n) * 128 + c0);
                o[0] = make_float4(vo[i][0], vo[i][1], vo[i][2], vo[i][3]);
                o[1] = make_float4(vo[i][4], vo[i][5], vo[i][6], vo[i][7]);
            }
            float4* s = reinterpret_cast<float4*>(Fs + (n0 + i) * 128 + c0);
            s[0] = make_float4(vo[i][0] * vp[0], vo[i][1] * vp[1], vo[i][2] * vp[2], vo[i][3] * vp[3]);
            s[1] = make_float4(vo[i][4] * vp[4], vo[i][5] * vp[5], vo[i][6] * vp[6], vo[i][7] * vp[7]);
        }
    }
    __syncthreads();

    // ---- view-attention score ----
    ull vac2[8][2];
    MBAR_WAIT(mb0, 1);
#pragma unroll
    for (int i = 0; i < 8; ++i) { vac2[i][0] = 0ull; vac2[i][1] = 0ull; }
    mm8x4_64(Fs, W0 + cg * 4, vac2, n0);
    {
        int cv = cg * 4;
        float4 vb = __ldg(reinterpret_cast<const float4*>(vattb1 + cv));
        float4 vw = __ldg(reinterpret_cast<const float4*>(vattW2 + cv));
#pragma unroll
        for (int i = 0; i < 8; ++i) {
            float2 f0 = u2f(vac2[i][0]), f1 = u2f(vac2[i][1]);
            float s = fmaxf(f0.x + vb.x, 0.f) * vw.x
                    + fmaxf(f0.y + vb.y, 0.f) * vw.y
                    + fmaxf(f1.x + vb.z, 0.f) * vw.z
                    + fmaxf(f1.y + vb.w, 0.f) * vw.w;
            red[cg * 128 + n0 + i] = s;
        }
    }
    __syncthreads();
    if (t < 128) {
        int n = nb + t;
        if (n < NN) {
            float s = __ldg(vattb2);
#pragma unroll
            for (int q = 0; q < 16; ++q) s += red[q * 128 + t];
            g_vscore[v * NN + n] = s;
        }
    }
}

// ---------------- fusion + residual + layer norm ----------------
// smem: [0:4) mbars | Zs 16384 | W0 16384 | W1 16384 | vwA 384 | redA 2048 | redB 2048 | muS 128 | rsS 128
__global__ void __launch_bounds__(NT, 1) k_fuse(
    const float* __restrict__ fusW, const float* __restrict__ fusb,
    const float* __restrict__ ln_g, const float* __restrict__ ln_b,
    float* __restrict__ out) {
    extern __shared__ float sm[];
    float* Zs = sm + 4;
    float* W0 = Zs + 16384;
    float* W1 = W0 + 16384;
    float* vwA = W1 + 16384;
    float* redA = vwA + 384;
    float* redB = redA + 2048;
    float* muS = redB + 2048;
    float* rsS = muS + 128;
    unsigned mb0 = smaddr(sm), mb1 = mb0 + 8;

    int nb = blockIdx.x * BN;
    int t = threadIdx.x;
    int ng = t >> 4, cg = t & 15;
    int n0 = ng * 8, c0 = cg * 8;

    if (t == 0) { MBAR_INIT(mb0); MBAR_INIT(mb1); }
    __syncthreads();
    if (t == 0) {
        MBAR_EXPECT(mb0, 65536u);
        bulk_g2s(smaddr(W0), fusW, 65536u, mb0);
        MBAR_EXPECT(mb1, 65536u);
        bulk_g2s(smaddr(W1), fusW + 16384, 65536u, mb1);
    }
    if (t < 128) {
        int n = nb + t;
        float s0 = 0.f, s1 = 0.f, s2 = 0.f, na = 0.f;
        if (n < NN) {
            s0 = g_vscore[n];
            s1 = g_vscore[NN + n];
            s2 = g_vscore[2 * NN + n];
            na = g_nodeatt[n];
        }
        float m = fmaxf(s0, fmaxf(s1, s2));
        float e0 = __expf(s0 - m), e1 = __expf(s1 - m), e2 = __expf(s2 - m);
        float inv = na / (e0 + e1 + e2);
        vwA[t] = e0 * inv;
        vwA[128 + t] = e1 * inv;
        vwA[256 + t] = e2 * inv;
    }
    load_tile_rm(g_selfout, nb, Zs);
    __syncthreads();

    // phase A: self_out @ fusW[0:128)
    ull acc2[8][4];
    MBAR_WAIT(mb0, 0);
    ZERO_ACC8x8(acc2);
    mm8x8<128, 128>(Zs, W0 + c0, acc2, n0);
    __syncthreads();   // done reading Zs

    // phase B: Zs = weighted tile
    {
#pragma unroll
        for (int r = 0; r < 16; ++r) {
            int idx = r * NT + t;
            int n = idx >> 5;
            int kq = idx & 31;
            float4 a = make_float4(0.f, 0.f, 0.f, 0.f);
            if (nb + n < NN) {
                float w0 = vwA[n], w1 = vwA[128 + n], w2 = vwA[256 + n];
                size_t gn = (size_t)(nb + n);
                float4 x0 = reinterpret_cast<const float4*>(g_viewout + gn * 128)[kq];
                float4 x1 = reinterpret_cast<const float4*>(g_viewout + ((size_t)NN + gn) * 128)[kq];
                float4 x2 = reinterpret_cast<const float4*>(g_viewout + ((size_t)2 * NN + gn) * 128)[kq];
                a.x = w0 * x0.x + w1 * x1.x + w2 * x2.x;
                a.y = w0 * x0.y + w1 * x1.y + w2 * x2.y;
                a.z = w0 * x0.z + w1 * x1.z + w2 * x2.z;
                a.w = w0 * x0.w + w1 * x1.w + w2 * x2.w;
            }
            reinterpret_cast<float4*>(Zs + n * 128)[kq] = a;
        }
    }
    __syncthreads();
    MBAR_WAIT(mb1, 0);
    mm8x8<128, 128>(Zs, W1 + c0, acc2, n0);

    // epilogue
    float fo[8][8];
    {
        float4 b0 = __ldg(reinterpret_cast<const float4*>(fusb + c0));
        float4 b1 = __ldg(reinterpret_cast<const float4*>(fusb + c0) + 1);
        float fb[8] = {b0.x, b0.y, b0.z, b0.w, b1.x, b1.y, b1.z, b1.w};
#pragma unroll
        for (int i = 0; i < 8; ++i) {
            int n = nb + n0 + i;
            float tr[8] = {0, 0, 0, 0, 0, 0, 0, 0};
            if (n < NN) {
                const float4* tp = reinterpret_cast<const float4*>(g_transformed + (size_t)n * 128 + c0);
                float4 t0 = tp[0], t1 = tp[1];
                tr[0] = t0.x; tr[1] = t0.y; tr[2] = t0.z; tr[3] = t0.w;
                tr[4] = t1.x; tr[5] = t1.y; tr[6] = t1.z; tr[7] = t1.w;
            }
            float lin[8];
#pragma unroll
            for (int jp = 0; jp < 4; ++jp) {
                float2 f2 = u2f(acc2[i][jp]);
                lin[2 * jp] = f2.x; lin[2 * jp + 1] = f2.y;
            }
            float s = 0.f, s2 = 0.f;
#pragma unroll
            for (int j = 0; j < 8; ++j) {
                float f = fmaxf(lin[j] + fb[j], 0.f) + tr[j];
                fo[i][j] = f;
                s += f;
                s2 = fmaf(f, f, s2);
            }
            redA[cg * 128 + n0 + i] = s;
            redB[cg * 128 + n0 + i] = s2;
        }
    }
    __syncthreads();
    if (t < 128) {
        float sa = 0.f, sb = 0.f;
#pragma unroll
        for (int q = 0; q < 16; ++q) {
            sa += redA[q * 128 + t];
            sb += redB[q * 128 + t];
        }
        float mu = sa * (1.f / 128.f);
        float var = sb * (1.f / 128.f) - mu * mu;
        muS[t] = mu;
        rsS[t] = rsqrtf(var + EPSL);
    }
    __syncthreads();
    {
        float4 lg0 = __ldg(reinterpret_cast<const float4*>(ln_g + c0));
        float4 lg1 = __ldg(reinterpret_cast<const float4*>(ln_g + c0) + 1);
        float4 lb0 = __ldg(reinterpret_cast<const float4*>(ln_b + c0));
        float4 lb1 = __ldg(reinterpret_cast<const float4*>(ln_b + c0) + 1);
        float lg[8] = {lg0.x, lg0.y, lg0.z, lg0.w, lg1.x, lg1.y, lg1.z, lg1.w};
        float lb[8] = {lb0.x, lb0.y, lb0.z, lb0.w, lb1.x, lb1.y, lb1.z, lb1.w};
#pragma unroll
        for (int i = 0; i < 8; ++i) {
            int nl = n0 + i, n = nb + nl;
            if (n < NN) {
                float mu = muS[nl], rs = rsS[nl];
                float o[8];
#pragma unroll
                for (int j = 0; j < 8; ++j)
                    o[j] = (fo[i][j] - mu) * rs * lg[j] + lb[j];
                float4* op = reinterpret_cast<float4*>(out + (size_t)n * 128 + c0);
                op[0] = make_float4(o[0], o[1], o[2], o[3]);
                op[1] = make_float4(o[4], o[5], o[6], o[7]);
            }
        }
    }
}

// ---------------- launch ----------------
extern "C" void kernel_launch(void* const* d_in, const int* in_sizes, int n_in,
                              void* d_out, int out_size) {
    const float* feats   = (const float*)d_in[0];
    const int*   esrc    = (const int*)d_in[1];
    const int*   edst    = (const int*)d_in[2];
    const float* ew      = (const float*)d_in[3];
    const float* clsW    = (const float*)d_in[4];
    const float* clsb    = (const float*)d_in[5];
    const float* attW1   = (const float*)d_in[6];
    const float* attb1   = (const float*)d_in[7];
    const float* attW2   = (const float*)d_in[8];
    const float* attb2   = (const float*)d_in[9];
    const float* attbias = (const float*)d_in[10];
    const float* relW    = (const float*)d_in[11];
    const float* relb    = (const float*)d_in[12];
    const float* gateW   = (const float*)d_in[13];
    const float* gateb   = (const float*)d_in[14];
    const float* vpref   = (const float*)d_in[15];
    const float* vattW1  = (const float*)d_in[16];
    const float* vattb1  = (const float*)d_in[17];
    const float* vattW2  = (const float*)d_in[18];
    const float* vattb2  = (const float*)d_in[19];
    const float* selfW   = (const float*)d_in[20];
    const float* selfb   = (const float*)d_in[21];
    const float* featW   = (const float*)d_in[22];
    const float* featb   = (const float*)d_in[23];
    const float* fusW    = (const float*)d_in[24];
    const float* fusb    = (const float*)d_in[25];
    const float* lng     = (const float*)d_in[26];
    const float* lnb     = (const float*)d_in[27];

    float* out = (float*)d_out;
    float* out_cp = out + (size_t)NN * 128;

    const int SMEM_FEAT = (4 + 16384 * 3 + 256 + 2048 + 256) * 4;
    const int SMEM_VIEW = (4 + 16384 * 3 + 128 + 2048) * 4;
    const int SMEM_FUSE = (4 + 16384 * 3 + 384 + 2048 + 2048 + 128 + 128) * 4;

    cudaFuncSetAttribute(k_feat, cudaFuncAttributeMaxDynamicSharedMemorySize, SMEM_FEAT);
    cudaFuncSetAttribute(k_view, cudaFuncAttributeMaxDynamicSharedMemorySize, SMEM_VIEW);
    cudaFuncSetAttribute(k_fuse, cudaFuncAttributeMaxDynamicSharedMemorySize, SMEM_FUSE);

    k_zero<<<2048, NT>>>();

    {
        long long warps = (long long)VV * EE;
        int blocks = (int)((warps * 32 + NT - 1) / NT);
        k_edge<<<blocks, NT>>>(esrc, edst, ew, feats);
    }

    k_feat<<<NTILES, NT, SMEM_FEAT>>>(feats, clsW, clsb, attW1, attb1, attW2, attb2,
                                      attbias, selfW, selfb, featW, featb, out_cp);

    dim3 gv(NTILES, VV);
    k_view<<<gv, NT, SMEM_VIEW>>>(relW, relb, gateW, gateb, vpref,
                                  vattW1, vattb1, vattW2, vattb2);

    k_fuse<<<NTILES, NT, SMEM_FUSE>>>(fusW, fusb, lng, lnb, out);
}

// round 5
// speedup vs baseline: 1.5032x; 1.1005x over previous
#include <cuda_runtime.h>
#include <cstdint>

// ---------------- problem constants ----------------
#define NN 100000
#define VV 3
#define EE 500000
#define EPSL 1e-5f

#define BN 128         // nodes per tile
#define NT 512         // threads per block (16 warps; warp = 8-node row group)
#define NTILES ((NN + BN - 1) / BN)   // 782

typedef unsigned long long ull;

// ---------------- scratch (device globals; no allocation) ----------------
__device__ float g_pre[(size_t)VV * NN * 128];
__device__ float g_wsum[VV * NN];
__device__ float g_selfout[(size_t)NN * 128];
__device__ float g_transformed[(size_t)NN * 128];
__device__ float g_nodeatt[NN];
__device__ float g_viewout[(size_t)VV * NN * 128];
__device__ float g_vscore[VV * NN];

// ---------------- small helpers ----------------
__device__ __forceinline__ void ffma2(ull &d, ull a, ull b) {
    asm("fma.rn.f32x2 %0, %1, %2, %0;" : "+l"(d) : "l"(a), "l"(b));
}
__device__ __forceinline__ ull fdup(float a) {
    ull r; asm("mov.b64 %0, {%1, %1};" : "=l"(r) : "f"(a)); return r;
}
__device__ __forceinline__ float2 u2f(ull v) {
    float2 r; asm("mov.b64 {%0, %1}, %2;" : "=f"(r.x), "=f"(r.y) : "l"(v)); return r;
}
__device__ __forceinline__ float sigm(float x) { return 1.f / (1.f + __expf(-x)); }

__device__ __forceinline__ unsigned smaddr(const void* p) {
    unsigned r;
    asm("{ .reg .u64 t; cvta.to.shared.u64 t, %1; cvt.u32.u64 %0, t; }" : "=r"(r) : "l"(p));
    return r;
}
#define MBAR_INIT(a) asm volatile("mbarrier.init.shared.b64 [%0], 1;" :: "r"(a))
#define MBAR_EXPECT(a, bytes) \
    asm volatile("mbarrier.arrive.expect_tx.shared.b64 _, [%0], %1;" :: "r"(a), "r"(bytes))
#define MBAR_WAIT(a, parity) do { \
    unsigned _p = 0; \
    while (!_p) { \
        asm volatile("{\n\t.reg .pred P;\n\t" \
                     "mbarrier.try_wait.parity.shared.b64 P, [%1], %2, 0x989680;\n\t" \
                     "selp.u32 %0, 1, 0, P;\n\t}" \
                     : "=r"(_p) : "r"(a), "r"((unsigned)(parity))); \
    } } while (0)

__device__ __forceinline__ void bulk_g2s(unsigned dst, const void* src, unsigned bytes, unsigned mbar) {
    asm volatile("cp.async.bulk.shared::cluster.global.mbarrier::complete_tx::bytes [%0], [%1], %2, [%3];"
                 :: "r"(dst), "l"(src), "r"(bytes), "r"(mbar) : "memory");
}

// warp xor-reduce over full warp (all lanes end with the sum)
__device__ __forceinline__ float wred32(float x) {
#pragma unroll
    for (int off = 16; off > 0; off >>= 1)
        x += __shfl_xor_sync(0xffffffffu, x, off);
    return x;
}
// reduce within 16-lane halves
__device__ __forceinline__ float wred16(float x) {
#pragma unroll
    for (int off = 8; off > 0; off >>= 1)
        x += __shfl_xor_sync(0xffffffffu, x, off);
    return x;
}

// ---------------- zero scratch ----------------
__global__ void k_zero() {
    size_t tid = (size_t)blockIdx.x * blockDim.x + threadIdx.x;
    size_t stride = (size_t)gridDim.x * blockDim.x;
    size_t total4 = ((size_t)VV * NN * 128) / 4;
    float4 z = make_float4(0.f, 0.f, 0.f, 0.f);
    for (size_t i = tid; i < total4; i += stride)
        reinterpret_cast<float4*>(g_pre)[i] = z;
    for (size_t i = tid; i < (size_t)VV * NN; i += stride)
        g_wsum[i] = 0.f;
}

// ---------------- edge scatter ----------------
__global__ void __launch_bounds__(256) k_edge(const int* __restrict__ src,
                                              const int* __restrict__ dst,
                                              const float* __restrict__ w,
                                              const float* __restrict__ feats) {
    int gw = (int)(((size_t)blockIdx.x * 256 + threadIdx.x) >> 5);
    if (gw >= VV * EE) return;
    int l = threadIdx.x & 31;
    int v = gw / EE;
    int s = src[gw];
    int d = dst[gw];
    float we = w[gw];
    float4 x = reinterpret_cast<const float4*>(feats + (size_t)s * 128)[l];
    float* p = g_pre + ((size_t)v * NN + d) * 128 + l * 4;
    asm volatile("red.global.add.v4.f32 [%0], {%1,%2,%3,%4};" ::
                 "l"(p), "f"(we * x.x), "f"(we * x.y), "f"(we * x.z), "f"(we * x.w)
                 : "memory");
    if (l == 0) atomicAdd(&g_wsum[v * NN + d], we);
}

// ---------------- warp-private tile loader ----------------
// warp ng loads rows n0..n0+7 of a [*,128] row-major matrix (coalesced 512B per row)
__device__ __forceinline__ void load_rows_warp(const float* __restrict__ g, int nb, int n0,
                                               int lane, float* __restrict__ Fs) {
#pragma unroll
    for (int i = 0; i < 8; ++i) {
        int n = nb + n0 + i;
        float4 v = make_float4(0.f, 0.f, 0.f, 0.f);
        if (n < NN) v = reinterpret_cast<const float4*>(g + (size_t)n * 128)[lane];
        reinterpret_cast<float4*>(Fs + (n0 + i) * 128)[lane] = v;
    }
}

// ---------------- 8x4 register-blocked matmul, FFMA2, broadcast A ----------------
// Fs row-major [128][128]; wbase = this thread's first output column; row stride BSTRIDE.
// acc2[i][j] = packed cols (c0+2j, c0+2j+1) for node n0+i.
template <int BSTRIDE>
__device__ __forceinline__ void mm8x4(const float* __restrict__ Fs, const float* __restrict__ wbase,
                                      ull acc2[8][2], int n0) {
#pragma unroll 2
    for (int kk = 0; kk < 128; kk += 4) {
        float4 a4[8];
#pragma unroll
        for (int i = 0; i < 8; ++i)
            a4[i] = *reinterpret_cast<const float4*>(Fs + (n0 + i) * 128 + kk);
#pragma unroll
        for (int q = 0; q < 4; ++q) {
            ulonglong2 b = *reinterpret_cast<const ulonglong2*>(wbase + (kk + q) * BSTRIDE);
#pragma unroll
            for (int i = 0; i < 8; ++i) {
                float av = (q == 0) ? a4[i].x : (q == 1) ? a4[i].y : (q == 2) ? a4[i].z : a4[i].w;
                ull ad = fdup(av);
                ffma2(acc2[i][0], ad, b.x);
                ffma2(acc2[i][1], ad, b.y);
            }
        }
    }
}

// 8x2 variant for OC=64 (view attention)
__device__ __forceinline__ void mm8x2_64(const float* __restrict__ Fs, const float* __restrict__ wbase,
                                         ull acc[8], int n0) {
#pragma unroll 2
    for (int kk = 0; kk < 128; kk += 4) {
        float4 a4[8];
#pragma unroll
        for (int i = 0; i < 8; ++i)
            a4[i] = *reinterpret_cast<const float4*>(Fs + (n0 + i) * 128 + kk);
#pragma unroll
        for (int q = 0; q < 4; ++q) {
            ull b = *reinterpret_cast<const ull*>(wbase + (kk + q) * 64);
#pragma unroll
            for (int i = 0; i < 8; ++i) {
                float av = (q == 0) ? a4[i].x : (q == 1) ? a4[i].y : (q == 2) ? a4[i].z : a4[i].w;
                ffma2(acc[i], fdup(av), b);
            }
        }
    }
}

#define ZERO_ACC(acc2) do { \
    _Pragma("unroll") for (int i = 0; i < 8; ++i) { acc2[i][0] = 0ull; acc2[i][1] = 0ull; } } while (0)

// ---------------- feature-side kernel ----------------
// smem: [0:4) mbars | Fs 16384 | W0 16384 | W1 16384 | clsWs 256 | scoreS 256
__global__ void __launch_bounds__(NT, 1) k_feat(
    const float* __restrict__ feats,
    const float* __restrict__ clsW, const float* __restrict__ clsb,
    const float* __restrict__ attW1, const float* __restrict__ attb1,
    const float* __restrict__ attW2, const float* __restrict__ attb2,
    const float* __restrict__ attbias,
    const float* __restrict__ selfW, const float* __restrict__ selfb,
    const float* __restrict__ featW, const float* __restrict__ featb,
    float* __restrict__ out_cp) {
    extern __shared__ float sm[];
    float* Fs = sm + 4;
    float* W0 = Fs + 16384;
    float* W1 = W0 + 16384;
    float* clsWs = W1 + 16384;
    float* scoreS = clsWs + 256;
    unsigned mb0 = smaddr(sm), mb1 = mb0 + 8;

    int nb = blockIdx.x * BN;
    int t = threadIdx.x;
    int lane = t & 31;
    int ng = t >> 5;              // warp id = row group
    int cg = lane;                // 0..31
    int n0 = ng * 8, c0 = cg * 4;

    if (t == 0) { MBAR_INIT(mb0); MBAR_INIT(mb1); }
    __syncthreads();
    if (t == 0) {
        MBAR_EXPECT(mb0, 65536u);
        bulk_g2s(smaddr(W0), selfW, 65536u, mb0);
        MBAR_EXPECT(mb1, 65536u);
        bulk_g2s(smaddr(W1), featW, 65536u, mb1);
    }
    load_rows_warp(feats, nb, n0, lane, Fs);
    if (t < 64)
        reinterpret_cast<float4*>(clsWs)[t] = __ldg(reinterpret_cast<const float4*>(clsW) + t);
    __syncwarp();

    ull acc2[8][2];

    // ---- self_out = f @ selfW + selfb ----
    MBAR_WAIT(mb0, 0);
    ZERO_ACC(acc2);
    mm8x4<128>(Fs, W0 + c0, acc2, n0);
    {
        float4 b0 = __ldg(reinterpret_cast<const float4*>(selfb + c0));
#pragma unroll
        for (int i = 0; i < 8; ++i) {
            int n = nb + n0 + i;
            if (n < NN) {
                float2 p0 = u2f(acc2[i][0]), p1 = u2f(acc2[i][1]);
                *reinterpret_cast<float4*>(g_selfout + (size_t)n * 128 + c0) =
                    make_float4(p0.x + b0.x, p0.y + b0.y, p1.x + b0.z, p1.y + b0.w);
            }
        }
    }
    __syncthreads();   // all warps done reading W0
    if (t == 0) {
        MBAR_EXPECT(mb0, 65536u);
        bulk_g2s(smaddr(W0), attW1, 65536u, mb0);   // [2][128][64] = 16384 floats
    }

    // ---- transformed = f @ featW + featb ----
    MBAR_WAIT(mb1, 0);
    ZERO_ACC(acc2);
    mm8x4<128>(Fs, W1 + c0, acc2, n0);
    {
        float4 b0 = __ldg(reinterpret_cast<const float4*>(featb + c0));
#pragma unroll
        for (int i = 0; i < 8; ++i) {
            int n = nb + n0 + i;
            if (n < NN) {
                float2 p0 = u2f(acc2[i][0]), p1 = u2f(acc2[i][1]);
                *reinterpret_cast<float4*>(g_transformed + (size_t)n * 128 + c0) =
                    make_float4(p0.x + b0.x, p0.y + b0.y, p1.x + b0.z, p1.y + b0.w);
            }
        }
    }

    // ---- label attention: h = relu(f @ attW1 + b1), score = sigm(h . attW2 + b2) ----
    // attW1 native [c][d][h]: this thread's cols live at base c*8192 + (c0&63), row stride 64
    MBAR_WAIT(mb0, 1);
    ZERO_ACC(acc2);
    {
        int cls = c0 >> 6;
        mm8x4<64>(Fs, W0 + cls * 8192 + (c0 & 63), acc2, n0);
        float4 ab = __ldg(reinterpret_cast<const float4*>(attb1 + c0));
        float4 aw = __ldg(reinterpret_cast<const float4*>(attW2 + c0));
        float b2v = __ldg(attb2 + cls);
#pragma unroll
        for (int i = 0; i < 8; ++i) {
            float2 f0 = u2f(acc2[i][0]), f1 = u2f(acc2[i][1]);
            float p = fmaxf(f0.x + ab.x, 0.f) * aw.x
                    + fmaxf(f0.y + ab.y, 0.f) * aw.y
                    + fmaxf(f1.x + ab.z, 0.f) * aw.z
                    + fmaxf(f1.y + ab.w, 0.f) * aw.w;
            p = wred16(p);          // sum over 16 lanes of this class half
            if ((lane & 15) == 0)
                scoreS[cls * 128 + n0 + i] = sigm(p + b2v);
        }
    }
    __syncthreads();

    // ---- class probs + node_att (threads 0..127, node = t) ----
    if (t < 128) {
        int nl = t, n = nb + nl;
        if (n < NN) {
            float l0 = __ldg(clsb), l1 = __ldg(clsb + 1);
#pragma unroll 8
            for (int q = 0; q < 32; ++q) {
                int kq = (q + nl) & 31;
                float4 f = reinterpret_cast<const float4*>(Fs + nl * 128)[kq];
                const float* cw = clsWs + kq * 8;
                l0 = fmaf(f.x, cw[0], l0); l1 = fmaf(f.x, cw[1], l1);
                l0 = fmaf(f.y, cw[2], l0); l1 = fmaf(f.y, cw[3], l1);
                l0 = fmaf(f.z, cw[4], l0); l1 = fmaf(f.z, cw[5], l1);
                l0 = fmaf(f.w, cw[6], l0); l1 = fmaf(f.w, cw[7], l1);
            }
            float m = fmaxf(l0, l1);
            float e0 = __expf(l0 - m), e1 = __expf(l1 - m);
            float inv = 1.f / (e0 + e1);
            float cp0 = e0 * inv, cp1 = e1 * inv;
            out_cp[(size_t)n * 2] = cp0;
            out_cp[(size_t)n * 2 + 1] = cp1;
            g_nodeatt[n] = scoreS[nl] * cp0 + scoreS[128 + nl] * cp1 + __ldg(attbias);
        }
    }
}

// ---------------- per-view kernel ----------------
// smem: [0:4) mbars | Fs 16384 | W0 16384 | W1 16384 | wsumS 128
__global__ void __launch_bounds__(NT, 1) k_view(
    const float* __restrict__ relW, const float* __restrict__ relb,
    const float* __restrict__ gateW, const float* __restrict__ gateb,
    const float* __restrict__ view_pref,
    const float* __restrict__ vattW1, const float* __restrict__ vattb1,
    const float* __restrict__ vattW2, const float* __restrict__ vattb2) {
    extern __shared__ float sm[];
    float* Fs = sm + 4;
    float* W0 = Fs + 16384;
    float* W1 = W0 + 16384;
    float* wsumS = W1 + 16384;
    unsigned mb0 = smaddr(sm), mb1 = mb0 + 8;

    int v = blockIdx.y;
    int nb = blockIdx.x * BN;
    int t = threadIdx.x;
    int lane = t & 31;
    int ng = t >> 5;
    int n0 = ng * 8, c0 = lane * 4;

    if (t == 0) { MBAR_INIT(mb0); MBAR_INIT(mb1); }
    __syncthreads();
    if (t == 0) {
        MBAR_EXPECT(mb0, 65536u);
        bulk_g2s(smaddr(W0), relW + (size_t)v * 16384, 65536u, mb0);
        MBAR_EXPECT(mb1, 65536u);
        bulk_g2s(smaddr(W1), gateW + (size_t)v * 16384, 65536u, mb1);
    }
    load_rows_warp(g_pre + (size_t)v * NN * 128, nb, n0, lane, Fs);
    if (t < 128) {
        int n = nb + t;
        wsumS[t] = (n < NN) ? g_wsum[v * NN + n] : 0.f;
    }
    __syncthreads();   // wsumS visible

    // ---- agg = pre @ relW + wsum * relb ----
    ull acc2[8][2];
    MBAR_WAIT(mb0, 0);
    ZERO_ACC(acc2);
    mm8x4<128>(Fs, W0 + c0, acc2, n0);
    {
        ulonglong2 r01 = __ldg(reinterpret_cast<const ulonglong2*>(relb + v * 128 + c0));
#pragma unroll
        for (int i = 0; i < 8; ++i) {
            ull wd = fdup(wsumS[n0 + i]);
            ffma2(acc2[i][0], wd, r01.x);
            ffma2(acc2[i][1], wd, r01.y);
        }
    }
    // stash agg into own rows of Fs (warp-private)
#pragma unroll
    for (int i = 0; i < 8; ++i) {
        float2 p0 = u2f(acc2[i][0]), p1 = u2f(acc2[i][1]);
        *reinterpret_cast<float4*>(Fs + (n0 + i) * 128 + c0) = make_float4(p0.x, p0.y, p1.x, p1.y);
    }
    __syncthreads();   // all warps done with W0 (relW) + own stash done
    if (t == 0) {
        MBAR_EXPECT(mb0, 32768u);
        bulk_g2s(smaddr(W0), vattW1, 32768u, mb0);   // [128][64] = 8192 floats
    }

    // ---- gate matmul on agg ----
    ull gac2[8][2];
    MBAR_WAIT(mb1, 0);
#pragma unroll
    for (int i = 0; i < 8; ++i) { gac2[i][0] = 0ull; gac2[i][1] = 0ull; }
    mm8x4<128>(Fs, W1 + c0, gac2, n0);

    // view_out = sigm(gate)*agg: store global + stash vo*vpref into Fs
    {
        float4 gb = __ldg(reinterpret_cast<const float4*>(gateb + v * 128 + c0));
        float4 vp = __ldg(reinterpret_cast<const float4*>(view_pref + v * 128 + c0));
#pragma unroll
        for (int i = 0; i < 8; ++i) {
            int n = nb + n0 + i;
            float2 g0 = u2f(gac2[i][0]), g1 = u2f(gac2[i][1]);
            float2 a0 = u2f(acc2[i][0]), a1 = u2f(acc2[i][1]);
            float vo0 = sigm(g0.x + gb.x) * a0.x;
            float vo1 = sigm(g0.y + gb.y) * a0.y;
            float vo2 = sigm(g1.x + gb.z) * a1.x;
            float vo3 = sigm(g1.y + gb.w) * a1.y;
            if (n < NN)
                *reinterpret_cast<float4*>(g_viewout + ((size_t)v * NN + n) * 128 + c0) =
                    make_float4(vo0, vo1, vo2, vo3);
            *reinterpret_cast<float4*>(Fs + (n0 + i) * 128 + c0) =
                make_float4(vo0 * vp.x, vo1 * vp.y, vo2 * vp.z, vo3 * vp.w);
        }
    }
    __syncwarp();

    // ---- view-attention score ----
    ull vac[8];
    MBAR_WAIT(mb0, 1);
#pragma unroll
    for (int i = 0; i < 8; ++i) vac[i] = 0ull;
    mm8x2_64(Fs, W0 + lane * 2, vac, n0);
    {
        int cv = lane * 2;
        float2 vb = __ldg(reinterpret_cast<const float2*>(vattb1 + cv));
        float2 vw = __ldg(reinterpret_cast<const float2*>(vattW2 + cv));
        float b2v = __ldg(vattb2);
#pragma unroll
        for (int i = 0; i < 8; ++i) {
            float2 f0 = u2f(vac[i]);
            float s = fmaxf(f0.x + vb.x, 0.f) * vw.x + fmaxf(f0.y + vb.y, 0.f) * vw.y;
            s = wred32(s);
            int n = nb + n0 + i;
            if (lane == 0 && n < NN) g_vscore[v * NN + n] = s + b2v;
        }
    }
}

// ---------------- fusion + residual + layer norm ----------------
// smem: [0:4) mbars | Zs 16384 | W0 16384 | W1 16384 | vwA 384
__global__ void __launch_bounds__(NT, 1) k_fuse(
    const float* __restrict__ fusW, const float* __restrict__ fusb,
    const float* __restrict__ ln_g, const float* __restrict__ ln_b,
    float* __restrict__ out) {
    extern __shared__ float sm[];
    float* Zs = sm + 4;
    float* W0 = Zs + 16384;
    float* W1 = W0 + 16384;
    float* vwA = W1 + 16384;
    unsigned mb0 = smaddr(sm), mb1 = mb0 + 8;

    int nb = blockIdx.x * BN;
    int t = threadIdx.x;
    int lane = t & 31;
    int ng = t >> 5;
    int n0 = ng * 8, c0 = lane * 4;

    if (t == 0) { MBAR_INIT(mb0); MBAR_INIT(mb1); }
    __syncthreads();
    if (t == 0) {
        MBAR_EXPECT(mb0, 65536u);
        bulk_g2s(smaddr(W0), fusW, 65536u, mb0);
        MBAR_EXPECT(mb1, 65536u);
        bulk_g2s(smaddr(W1), fusW + 16384, 65536u, mb1);
    }
    if (t < 128) {
        int n = nb + t;
        float s0 = 0.f, s1 = 0.f, s2 = 0.f, na = 0.f;
        if (n < NN) {
            s0 = g_vscore[n];
            s1 = g_vscore[NN + n];
            s2 = g_vscore[2 * NN + n];
            na = g_nodeatt[n];
        }
        float m = fmaxf(s0, fmaxf(s1, s2));
        float e0 = __expf(s0 - m), e1 = __expf(s1 - m), e2 = __expf(s2 - m);
        float inv = na / (e0 + e1 + e2);
        vwA[t] = e0 * inv;
        vwA[128 + t] = e1 * inv;
        vwA[256 + t] = e2 * inv;
    }
    load_rows_warp(g_selfout, nb, n0, lane, Zs);
    __syncthreads();   // vwA visible

    // phase A: self_out @ fusW[0:128)
    ull acc2[8][2];
    MBAR_WAIT(mb0, 0);
    ZERO_ACC(acc2);
    mm8x4<128>(Zs, W0 + c0, acc2, n0);

    // phase B: rebuild own rows of Zs = weighted view combo (warp-private)
#pragma unroll
    for (int i = 0; i < 8; ++i) {
        int nl = n0 + i;
        int n = nb + nl;
        float4 a = make_float4(0.f, 0.f, 0.f, 0.f);
        if (n < NN) {
            float w0 = vwA[nl], w1 = vwA[128 + nl], w2 = vwA[256 + nl];
            float4 x0 = reinterpret_cast<const float4*>(g_viewout + (size_t)n * 128)[lane];
            float4 x1 = reinterpret_cast<const float4*>(g_viewout + ((size_t)NN + n) * 128)[lane];
            float4 x2 = reinterpret_cast<const float4*>(g_viewout + ((size_t)2 * NN + n) * 128)[lane];
            a.x = w0 * x0.x + w1 * x1.x + w2 * x2.x;
            a.y = w0 * x0.y + w1 * x1.y + w2 * x2.y;
            a.z = w0 * x0.z + w1 * x1.z + w2 * x2.z;
            a.w = w0 * x0.w + w1 * x1.w + w2 * x2.w;
        }
        reinterpret_cast<float4*>(Zs + nl * 128)[lane] = a;
    }
    __syncwarp();
    MBAR_WAIT(mb1, 0);
    mm8x4<128>(Zs, W1 + c0, acc2, n0);

    // epilogue: relu(+fusb) + transformed, LN via warp reduce
    {
        float4 fb = __ldg(reinterpret_cast<const float4*>(fusb + c0));
        float4 lg = __ldg(reinterpret_cast<const float4*>(ln_g + c0));
        float4 lb = __ldg(reinterpret_cast<const float4*>(ln_b + c0));
#pragma unroll
        for (int i = 0; i < 8; ++i) {
            int n = nb + n0 + i;
            if (n >= NN) continue;   // uniform across warp
            float4 tr = *reinterpret_cast<const float4*>(g_transformed + (size_t)n * 128 + c0);
            float2 l0 = u2f(acc2[i][0]), l1 = u2f(acc2[i][1]);
            float f0 = fmaxf(l0.x + fb.x, 0.f) + tr.x;
            float f1 = fmaxf(l0.y + fb.y, 0.f) + tr.y;
            float f2 = fmaxf(l1.x + fb.z, 0.f) + tr.z;
            float f3 = fmaxf(l1.y + fb.w, 0.f) + tr.w;
            float s = f0 + f1 + f2 + f3;
            float s2 = f0 * f0 + f1 * f1 + f2 * f2 + f3 * f3;
            s = wred32(s);
            s2 = wred32(s2);
            float mu = s * (1.f / 128.f);
            float var = s2 * (1.f / 128.f) - mu * mu;
            float rs = rsqrtf(var + EPSL);
            *reinterpret_cast<float4*>(out + (size_t)n * 128 + c0) =
                make_float4((f0 - mu) * rs * lg.x + lb.x,
                            (f1 - mu) * rs * lg.y + lb.y,
                            (f2 - mu) * rs * lg.z + lb.z,
                            (f3 - mu) * rs * lg.w + lb.w);
        }
    }
}

// ---------------- launch ----------------
extern "C" void kernel_launch(void* const* d_in, const int* in_sizes, int n_in,
                              void* d_out, int out_size) {
    const float* feats   = (const float*)d_in[0];
    const int*   esrc    = (const int*)d_in[1];
    const int*   edst    = (const int*)d_in[2];
    const float* ew      = (const float*)d_in[3];
    const float* clsW    = (const float*)d_in[4];
    const float* clsb    = (const float*)d_in[5];
    const float* attW1   = (const float*)d_in[6];
    const float* attb1   = (const float*)d_in[7];
    const float* attW2   = (const float*)d_in[8];
    const float* attb2   = (const float*)d_in[9];
    const float* attbias = (const float*)d_in[10];
    const float* relW    = (const float*)d_in[11];
    const float* relb    = (const float*)d_in[12];
    const float* gateW   = (const float*)d_in[13];
    const float* gateb   = (const float*)d_in[14];
    const float* vpref   = (const float*)d_in[15];
    const float* vattW1  = (const float*)d_in[16];
    const float* vattb1  = (const float*)d_in[17];
    const float* vattW2  = (const float*)d_in[18];
    const float* vattb2  = (const float*)d_in[19];
    const float* selfW   = (const float*)d_in[20];
    const float* selfb   = (const float*)d_in[21];
    const float* featW   = (const float*)d_in[22];
    const float* featb   = (const float*)d_in[23];
    const float* fusW    = (const float*)d_in[24];
    const float* fusb    = (const float*)d_in[25];
    const float* lng     = (const float*)d_in[26];
    const float* lnb     = (const float*)d_in[27];

    float* out = (float*)d_out;
    float* out_cp = out + (size_t)NN * 128;

    const int SMEM_FEAT = (4 + 16384 * 3 + 256 + 256) * 4;
    const int SMEM_VIEW = (4 + 16384 * 3 + 128) * 4;
    const int SMEM_FUSE = (4 + 16384 * 3 + 384) * 4;

    cudaFuncSetAttribute(k_feat, cudaFuncAttributeMaxDynamicSharedMemorySize, SMEM_FEAT);
    cudaFuncSetAttribute(k_view, cudaFuncAttributeMaxDynamicSharedMemorySize, SMEM_VIEW);
    cudaFuncSetAttribute(k_fuse, cudaFuncAttributeMaxDynamicSharedMemorySize, SMEM_FUSE);

    k_zero<<<2048, 256>>>();

    {
        long long warps = (long long)VV * EE;
        int blocks = (int)((warps * 32 + 255) / 256);
        k_edge<<<blocks, 256>>>(esrc, edst, ew, feats);
    }

    k_feat<<<NTILES, NT, SMEM_FEAT>>>(feats, clsW, clsb, attW1, attb1, attW2, attb2,
                                      attbias, selfW, selfb, featW, featb, out_cp);

    dim3 gv(NTILES, VV);
    k_view<<<gv, NT, SMEM_VIEW>>>(relW, relb, gateW, gateb, vpref,
                                  vattW1, vattb1, vattW2, vattb2);

    k_fuse<<<NTILES, NT, SMEM_FUSE>>>(fusW, fusb, lng, lnb, out);
}